// round 13
// baseline (speedup 1.0000x reference)
#include <cuda_runtime.h>
#include <cuda_bf16.h>
#include <cuda_fp16.h>
#include <cstdint>

#define S_LEN 4096
#define DM    768
#define NH    12
#define DK    64

// ---------------- scratch (device globals) ----------------
__device__ __nv_bfloat16 g_xh[S_LEN * DM],  g_xl[S_LEN * DM];
__device__ __nv_bfloat16 g_Wqh[DM * DM],    g_Wql[DM * DM];
__device__ __nv_bfloat16 g_Wkh[DM * DM],    g_Wkl[DM * DM];
__device__ __nv_bfloat16 g_Wvh[DM * DM],    g_Wvl[DM * DM];
__device__ __nv_bfloat16 g_Woh[DM * DM],    g_Wol[DM * DM];
__device__ __nv_bfloat16 g_Qh[S_LEN * DM],  g_Ql[S_LEN * DM];   // [s][hd]
__device__ __nv_bfloat16 g_Kh[S_LEN * DM],  g_Kl[S_LEN * DM];   // [s][hd]
__device__ __half        g_Vt[DM * S_LEN];                      // [hd][s], fp16
__device__ __nv_bfloat16 g_ctxh[S_LEN * DM], g_ctxl[S_LEN * DM];

// ---------------- helpers ----------------
__device__ __forceinline__ uint32_t smem_u32(const void* p) {
    uint32_t a;
    asm("{ .reg .u64 t; cvta.to.shared.u64 t, %1; cvt.u32.u64 %0, t; }"
        : "=r"(a) : "l"(p));
    return a;
}
__device__ __forceinline__ void ldsm_x4(uint32_t* r, uint32_t addr) {
    asm volatile("ldmatrix.sync.aligned.m8n8.x4.shared.b16 {%0,%1,%2,%3}, [%4];"
                 : "=r"(r[0]), "=r"(r[1]), "=r"(r[2]), "=r"(r[3]) : "r"(addr));
}
__device__ __forceinline__ void mma_bf16(float* d, const uint32_t* a,
                                         uint32_t b0, uint32_t b1) {
    asm volatile("mma.sync.aligned.m16n8k16.row.col.f32.bf16.bf16.f32 "
                 "{%0,%1,%2,%3}, {%4,%5,%6,%7}, {%8,%9}, {%0,%1,%2,%3};"
                 : "+f"(d[0]), "+f"(d[1]), "+f"(d[2]), "+f"(d[3])
                 : "r"(a[0]), "r"(a[1]), "r"(a[2]), "r"(a[3]), "r"(b0), "r"(b1));
}
__device__ __forceinline__ void mma_fp16(float* d, const uint32_t* a,
                                         uint32_t b0, uint32_t b1) {
    asm volatile("mma.sync.aligned.m16n8k16.row.col.f32.f16.f16.f32 "
                 "{%0,%1,%2,%3}, {%4,%5,%6,%7}, {%8,%9}, {%0,%1,%2,%3};"
                 : "+f"(d[0]), "+f"(d[1]), "+f"(d[2]), "+f"(d[3])
                 : "r"(a[0]), "r"(a[1]), "r"(a[2]), "r"(a[3]), "r"(b0), "r"(b1));
}
__device__ __forceinline__ void sts_v4(uint32_t addr, uint4 v) {
    asm volatile("st.shared.v4.b32 [%0], {%1, %2, %3, %4};"
                 :: "r"(addr), "r"(v.x), "r"(v.y), "r"(v.z), "r"(v.w) : "memory");
}
__device__ __forceinline__ void split2(float x, float y, uint32_t& hi, uint32_t& lo) {
    __nv_bfloat16 hx = __float2bfloat16(x), hy = __float2bfloat16(y);
    __nv_bfloat162 h2 = {hx, hy};
    hi = *(uint32_t*)&h2;
    __nv_bfloat162 l2 = {__float2bfloat16(x - __bfloat162float(hx)),
                         __float2bfloat16(y - __bfloat162float(hy))};
    lo = *(uint32_t*)&l2;
}
__device__ __forceinline__ uint32_t pack_h2(float x, float y) {
    __half2 h = __floats2half2_rn(x, y);
    return *(uint32_t*)&h;
}
__device__ __forceinline__ float round_h(float x) {
    return __half2float(__float2half_rn(x));
}
__device__ __forceinline__ void cp_async16(uint32_t dst, const void* src) {
    asm volatile("cp.async.cg.shared.global [%0], [%1], 16;"
                 :: "r"(dst), "l"(src));
}
#define CP_COMMIT() asm volatile("cp.async.commit_group;" ::: "memory")
#define CP_WAIT0()  asm volatile("cp.async.wait_group 0;" ::: "memory")

// ---------------- single fp32 -> bf16 hi/lo split pass for all 5 tensors ----
#define NX4 (S_LEN * DM / 4)
#define NW4 (DM * DM / 4)

__global__ __launch_bounds__(256)
void split_all(const float* __restrict__ x,  const float* __restrict__ Wq,
               const float* __restrict__ Wk, const float* __restrict__ Wv,
               const float* __restrict__ Wo)
{
    int i = blockIdx.x * blockDim.x + threadIdx.x;
    const float* in;
    __nv_bfloat16 *hi, *lo;
    int j = i;
    if (j < NX4)            { in = x;  hi = g_xh;  lo = g_xl;  }
    else if ((j -= NX4) < NW4)   { in = Wq; hi = g_Wqh; lo = g_Wql; }
    else if ((j -= NW4) < NW4)   { in = Wk; hi = g_Wkh; lo = g_Wkl; }
    else if ((j -= NW4) < NW4)   { in = Wv; hi = g_Wvh; lo = g_Wvl; }
    else if ((j -= NW4) < NW4)   { in = Wo; hi = g_Woh; lo = g_Wol; }
    else return;
    float4 v = ((const float4*)in)[j];
    uint32_t h0, l0, h1, l1;
    split2(v.x, v.y, h0, l0);
    split2(v.z, v.w, h1, l1);
    ((uint2*)hi)[j] = make_uint2(h0, h1);
    ((uint2*)lo)[j] = make_uint2(l0, l1);
}

// ===========================================================================
// bf16x3 GEMM body (unchanged from R12)
// ===========================================================================
#define ROWB      80
#define TILE_A    (128 * ROWB)

template<int OMODE, int BNR>
__device__ __forceinline__
void gemm_body(const __nv_bfloat16* __restrict__ Ah, const __nv_bfloat16* __restrict__ Al,
               const __nv_bfloat16* __restrict__ Bh, const __nv_bfloat16* __restrict__ Bl,
               float* __restrict__ C,
               __nv_bfloat16* __restrict__ Ch, __nv_bfloat16* __restrict__ Cl,
               __half* __restrict__ Cf16,
               int M, int N, int K, int bm, int bn, uint32_t sbase)
{
    constexpr int TILE_BB = BNR * ROWB;
    constexpr int BUF_B   = 2 * TILE_A + 2 * TILE_BB;
    constexpr int AHI = 0, ALO = TILE_A, BHI = 2 * TILE_A, BLO = 2 * TILE_A + TILE_BB;
    constexpr int NF = BNR / 16;
    constexpr int NCP = (1024 + BNR * 8) / 256;

    const int tid  = threadIdx.x;
    const int lane = tid & 31;
    const int warp = tid >> 5;
    const int m0 = (warp >> 1) * 32;
    const int n0 = (warp & 1) * (BNR / 2);

    float acc[2][NF][4];
    #pragma unroll
    for (int mt = 0; mt < 2; mt++)
        #pragma unroll
        for (int nf = 0; nf < NF; nf++)
            #pragma unroll
            for (int e = 0; e < 4; e++) acc[mt][nf][e] = 0.0f;

    const int nchunk = K / 32;

    auto issue = [&](int c) {
        const uint32_t buf = sbase + (uint32_t)(c & 1) * BUF_B;
        const int kc = c * 32;
        #pragma unroll
        for (int j = 0; j < NCP; j++) {
            const int idx = tid + j * 256;
            uint32_t dst;
            const __nv_bfloat16* src;
            if (idx < 512) {
                const int row = idx >> 2, ch = idx & 3;
                dst = buf + AHI + row * ROWB + ch * 16;
                src = &Ah[(size_t)(bm + row) * K + kc + ch * 8];
            } else if (idx < 1024) {
                const int r2 = idx - 512;
                const int row = r2 >> 2, ch = r2 & 3;
                dst = buf + ALO + row * ROWB + ch * 16;
                src = &Al[(size_t)(bm + row) * K + kc + ch * 8];
            } else if (idx < 1024 + BNR * 4) {
                const int r2 = idx - 1024;
                const int row = r2 >> 2, ch = r2 & 3;
                dst = buf + BHI + row * ROWB + ch * 16;
                src = &Bh[(size_t)(bn + row) * K + kc + ch * 8];
            } else {
                const int r2 = idx - (1024 + BNR * 4);
                const int row = r2 >> 2, ch = r2 & 3;
                dst = buf + BLO + row * ROWB + ch * 16;
                src = &Bl[(size_t)(bn + row) * K + kc + ch * 8];
            }
            cp_async16(dst, src);
        }
        CP_COMMIT();
    };

    issue(0);

    const uint32_t lrow = (lane & 15);
    const uint32_t koff = (lane >> 4) * 16;

    for (int c = 0; c < nchunk; ++c) {
        CP_WAIT0();
        __syncthreads();
        if (c + 1 < nchunk) issue(c + 1);

        const uint32_t buf = sbase + (uint32_t)(c & 1) * BUF_B;
        #pragma unroll
        for (int ks = 0; ks < 2; ks++) {
            const uint32_t kb = ks * 32 + koff;
            uint32_t ah[2][4], al[2][4];
            #pragma unroll
            for (int mt = 0; mt < 2; mt++) {
                const uint32_t ro = (uint32_t)(m0 + mt * 16 + lrow) * ROWB + kb;
                ldsm_x4(ah[mt], buf + AHI + ro);
                ldsm_x4(al[mt], buf + ALO + ro);
            }
            uint32_t bh[NF / 2][4], bl[NF / 2][4];
            #pragma unroll
            for (int g = 0; g < NF / 2; g++) {
                const uint32_t ro = (uint32_t)(n0 + g * 16 + lrow) * ROWB + kb;
                ldsm_x4(bh[g], buf + BHI + ro);
                ldsm_x4(bl[g], buf + BLO + ro);
            }
            #pragma unroll
            for (int mt = 0; mt < 2; mt++) {
                #pragma unroll
                for (int g = 0; g < NF / 2; g++) {
                    mma_bf16(acc[mt][g * 2 + 0], ah[mt], bh[g][0], bh[g][2]);
                    mma_bf16(acc[mt][g * 2 + 0], ah[mt], bl[g][0], bl[g][2]);
                    mma_bf16(acc[mt][g * 2 + 0], al[mt], bh[g][0], bh[g][2]);
                    mma_bf16(acc[mt][g * 2 + 1], ah[mt], bh[g][1], bh[g][3]);
                    mma_bf16(acc[mt][g * 2 + 1], ah[mt], bl[g][1], bl[g][3]);
                    mma_bf16(acc[mt][g * 2 + 1], al[mt], bh[g][1], bh[g][3]);
                }
            }
        }
        __syncthreads();
    }

    #pragma unroll
    for (int mt = 0; mt < 2; mt++) {
        const int row = bm + m0 + mt * 16 + (lane >> 2);
        #pragma unroll
        for (int nf = 0; nf < NF; nf++) {
            const int col = bn + n0 + nf * 8 + (lane & 3) * 2;
            if (OMODE == 0) {
                *(float2*)&C[(size_t)row * N + col] =
                    make_float2(acc[mt][nf][0], acc[mt][nf][1]);
                *(float2*)&C[(size_t)(row + 8) * N + col] =
                    make_float2(acc[mt][nf][2], acc[mt][nf][3]);
            } else if (OMODE == 1) {
                uint32_t h0, l0, h1, l1;
                split2(acc[mt][nf][0], acc[mt][nf][1], h0, l0);
                split2(acc[mt][nf][2], acc[mt][nf][3], h1, l1);
                *(uint32_t*)&Ch[(size_t)row * N + col]       = h0;
                *(uint32_t*)&Cl[(size_t)row * N + col]       = l0;
                *(uint32_t*)&Ch[(size_t)(row + 8) * N + col] = h1;
                *(uint32_t*)&Cl[(size_t)(row + 8) * N + col] = l1;
            } else {
                *(uint32_t*)&Cf16[(size_t)row * N + col] =
                    pack_h2(acc[mt][nf][0], acc[mt][nf][1]);
                *(uint32_t*)&Cf16[(size_t)(row + 8) * N + col] =
                    pack_h2(acc[mt][nf][2], acc[mt][nf][3]);
            }
        }
    }
}

#define GEMM_SMEM_128 (2 * (2 * TILE_A + 2 * 128 * ROWB))   // 81920
#define GEMM_SMEM_64  (2 * (2 * TILE_A + 2 * 64 * ROWB))    // 61440

__global__ __launch_bounds__(256, 2)
void gemm_qkv()
{
    extern __shared__ __align__(128) char dynsm[];
    const uint32_t sbase = smem_u32(dynsm);
    const int z = blockIdx.z;

    if (z == 0) {
        gemm_body<1, 128>(g_xh, g_xl, g_Wqh, g_Wql, nullptr, g_Qh, g_Ql, nullptr,
                          S_LEN, DM, DM, blockIdx.x * 128, blockIdx.y * 128, sbase);
    } else if (z == 1) {
        gemm_body<1, 128>(g_xh, g_xl, g_Wkh, g_Wkl, nullptr, g_Kh, g_Kl, nullptr,
                          S_LEN, DM, DM, blockIdx.x * 128, blockIdx.y * 128, sbase);
    } else {
        gemm_body<2, 128>(g_Wvh, g_Wvl, g_xh, g_xl, nullptr, nullptr, nullptr, g_Vt,
                          DM, S_LEN, DM, blockIdx.y * 128, blockIdx.x * 128, sbase);
    }
}

__global__ __launch_bounds__(256, 2)
void gemm_out(float* __restrict__ out)
{
    extern __shared__ __align__(128) char dynsm[];
    const uint32_t sbase = smem_u32(dynsm);
    gemm_body<0, 64>(g_ctxh, g_ctxl, g_Woh, g_Wol, out, nullptr, nullptr, nullptr,
                     S_LEN, DM, DM, blockIdx.x * 128, blockIdx.y * 64, sbase);
}

// ===========================================================================
// Tensor-core causal flash attention — 256-row Q tile, 8 warps x 32 q-rows,
// 1 CTA/SM. QK bf16x3, PV single fp16 (P fp16-exact, l from rounded P).
// Halves K/V smem-read duplication per unit work vs R12. Bit-identical math.
// ===========================================================================
#define AROWB 144
#define AQH   0
#define AQL   (256 * AROWB)              // 36864
#define AKV   (2 * 256 * AROWB)          // 73728
#define KVSTG 24576                      // Kh 8K + Kl 8K + V 8K
#define KH_O  0
#define KL_O  8192
#define V_O   16384
#define ATTN_SMEM (AKV + 2 * KVSTG)      // 122880

__global__ __launch_bounds__(256, 1)
void attn_tc()
{
    extern __shared__ __align__(128) char dynbuf[];
    const uint32_t sb = smem_u32(dynbuf);

    const int tid  = threadIdx.x;
    const int lane = tid & 31;
    const int warp = tid >> 5;
    const int wr   = warp * 32;                 // warp covers 32 q-rows
    // Global LPT over 16 qb-tiles x 12 heads
    const int rank = blockIdx.x;
    const int qb   = (S_LEN / 256) - 1 - rank / NH;   // 15..0
    const int h    = rank % NH;
    const int q0   = qb * 256;

    // ---- load Q tile (256 rows, hi/lo) ----
    {
        const int gr = tid >> 3;
        const int gc = tid & 7;
        #pragma unroll
        for (int i = 0; i < 8; i++) {
            const int r = gr + i * 32;          // 0..255
            const uint32_t soff = (uint32_t)r * AROWB + gc * 16;
            uint4 vh = *(const uint4*)&g_Qh[(size_t)(q0 + r) * DM + h * 64 + gc * 8];
            uint4 vl = *(const uint4*)&g_Ql[(size_t)(q0 + r) * DM + h * 64 + gc * 8];
            sts_v4(sb + AQH + soff, vh);
            sts_v4(sb + AQL + soff, vl);
        }
    }

    auto issue_kv = [&](int t) {
        const uint32_t kvb = sb + AKV + (uint32_t)(t & 1) * KVSTG;
        const int k0 = t * 64;
        #pragma unroll
        for (int j = 0; j < 6; j++) {
            const int idx = tid + j * 256;      // 0..1535
            const int arr = idx >> 9;           // 0:Kh 1:Kl 2:V
            const int rem = idx & 511;
            const int row = rem >> 3;
            const int c   = rem & 7;
            const uint32_t dst = kvb + (uint32_t)arr * 8192 + row * 128 +
                                 ((uint32_t)(c ^ (row & 7)) << 4);
            const void* src;
            if (arr == 0)      src = &g_Kh[(size_t)(k0 + row) * DM + h * 64 + c * 8];
            else if (arr == 1) src = &g_Kl[(size_t)(k0 + row) * DM + h * 64 + c * 8];
            else               src = &g_Vt[(size_t)(h * 64 + row) * S_LEN + k0 + c * 8];
            cp_async16(dst, src);
        }
        CP_COMMIT();
    };

    issue_kv(0);

    float o[2][8][4];
    #pragma unroll
    for (int mt = 0; mt < 2; mt++)
        #pragma unroll
        for (int f = 0; f < 8; f++)
            #pragma unroll
            for (int e = 0; e < 4; e++) o[mt][f][e] = 0.0f;
    float m_s[2][2] = {{-1e30f, -1e30f}, {-1e30f, -1e30f}};
    float l_s[2][2] = {{0.0f, 0.0f}, {0.0f, 0.0f}};

    int row0[2];
    row0[0] = q0 + wr + (lane >> 2);
    row0[1] = row0[0] + 16;
    const uint32_t lrow = (lane & 15);
    const uint32_t koff = (lane >> 4) * 16;
    const int ntile = 4 * qb + 4;

    for (int t = 0; t < ntile; ++t) {
        const int k0 = t * 64;
        CP_WAIT0();
        __syncthreads();
        if (t + 1 < ntile) issue_kv(t + 1);

        const uint32_t kvb = sb + AKV + (uint32_t)(t & 1) * KVSTG;

        float sacc[2][8][4];
        #pragma unroll
        for (int mt = 0; mt < 2; mt++)
            #pragma unroll
            for (int f = 0; f < 8; f++)
                #pragma unroll
                for (int e = 0; e < 4; e++) sacc[mt][f][e] = 0.0f;

        // ---- S = Q K^T (bf16x3) ----
        #pragma unroll
        for (int ks = 0; ks < 4; ks++) {
            uint32_t qh[2][4], ql[2][4];
            #pragma unroll
            for (int mt = 0; mt < 2; mt++) {
                const uint32_t qoff =
                    (uint32_t)(wr + mt * 16 + lrow) * AROWB + ks * 32 + koff;
                ldsm_x4(qh[mt], sb + AQH + qoff);
                ldsm_x4(ql[mt], sb + AQL + qoff);
            }
            const uint32_t cidx = ks * 2 + (lane >> 4);
            #pragma unroll
            for (int g = 0; g < 4; g++) {
                const uint32_t row = g * 16 + lrow;
                const uint32_t ro = row * 128 + ((cidx ^ (row & 7)) << 4);
                uint32_t kh[4], kl[4];
                ldsm_x4(kh, kvb + KH_O + ro);
                ldsm_x4(kl, kvb + KL_O + ro);
                #pragma unroll
                for (int mt = 0; mt < 2; mt++) {
                    mma_bf16(sacc[mt][g * 2 + 0], qh[mt], kh[0], kh[2]);
                    mma_bf16(sacc[mt][g * 2 + 0], qh[mt], kl[0], kl[2]);
                    mma_bf16(sacc[mt][g * 2 + 0], ql[mt], kh[0], kh[2]);
                    mma_bf16(sacc[mt][g * 2 + 1], qh[mt], kh[1], kh[3]);
                    mma_bf16(sacc[mt][g * 2 + 1], qh[mt], kl[1], kl[3]);
                    mma_bf16(sacc[mt][g * 2 + 1], ql[mt], kh[1], kh[3]);
                }
            }
        }

        // ---- scale + causal mask ----
        const float scale = 0.125f;
        if (t >= 4 * qb) {
            #pragma unroll
            for (int mt = 0; mt < 2; mt++) {
                const int r0 = row0[mt], r1 = row0[mt] + 8;
                #pragma unroll
                for (int f = 0; f < 8; f++) {
                    const int cb = k0 + f * 8 + (lane & 3) * 2;
                    sacc[mt][f][0] = (cb     > r0) ? -1e30f : sacc[mt][f][0] * scale;
                    sacc[mt][f][1] = (cb + 1 > r0) ? -1e30f : sacc[mt][f][1] * scale;
                    sacc[mt][f][2] = (cb     > r1) ? -1e30f : sacc[mt][f][2] * scale;
                    sacc[mt][f][3] = (cb + 1 > r1) ? -1e30f : sacc[mt][f][3] * scale;
                }
            }
        } else {
            #pragma unroll
            for (int mt = 0; mt < 2; mt++)
                #pragma unroll
                for (int f = 0; f < 8; f++)
                    #pragma unroll
                    for (int e = 0; e < 4; e++) sacc[mt][f][e] *= scale;
        }

        // ---- online softmax (per mt: rows r0, r1) ----
        #pragma unroll
        for (int mt = 0; mt < 2; mt++) {
            float rm0 = -1e30f, rm1 = -1e30f;
            #pragma unroll
            for (int f = 0; f < 8; f++) {
                rm0 = fmaxf(rm0, fmaxf(sacc[mt][f][0], sacc[mt][f][1]));
                rm1 = fmaxf(rm1, fmaxf(sacc[mt][f][2], sacc[mt][f][3]));
            }
            #pragma unroll
            for (int off = 1; off < 4; off <<= 1) {
                rm0 = fmaxf(rm0, __shfl_xor_sync(0xffffffffu, rm0, off));
                rm1 = fmaxf(rm1, __shfl_xor_sync(0xffffffffu, rm1, off));
            }
            const float mn0 = fmaxf(m_s[mt][0], rm0);
            const float mn1 = fmaxf(m_s[mt][1], rm1);
            const float al0 = __expf(m_s[mt][0] - mn0);
            const float al1 = __expf(m_s[mt][1] - mn1);
            float rs0 = 0.0f, rs1 = 0.0f;
            #pragma unroll
            for (int f = 0; f < 8; f++) {
                sacc[mt][f][0] = round_h(__expf(sacc[mt][f][0] - mn0));
                sacc[mt][f][1] = round_h(__expf(sacc[mt][f][1] - mn0));
                sacc[mt][f][2] = round_h(__expf(sacc[mt][f][2] - mn1));
                sacc[mt][f][3] = round_h(__expf(sacc[mt][f][3] - mn1));
                rs0 += sacc[mt][f][0] + sacc[mt][f][1];
                rs1 += sacc[mt][f][2] + sacc[mt][f][3];
            }
            #pragma unroll
            for (int off = 1; off < 4; off <<= 1) {
                rs0 += __shfl_xor_sync(0xffffffffu, rs0, off);
                rs1 += __shfl_xor_sync(0xffffffffu, rs1, off);
            }
            l_s[mt][0] = l_s[mt][0] * al0 + rs0;
            l_s[mt][1] = l_s[mt][1] * al1 + rs1;
            m_s[mt][0] = mn0;
            m_s[mt][1] = mn1;
            #pragma unroll
            for (int f = 0; f < 8; f++) {
                o[mt][f][0] *= al0; o[mt][f][1] *= al0;
                o[mt][f][2] *= al1; o[mt][f][3] *= al1;
            }
        }

        // ---- O += P V : single fp16 mma ----
        #pragma unroll
        for (int ks = 0; ks < 4; ks++) {
            uint32_t ph[2][4];
            #pragma unroll
            for (int mt = 0; mt < 2; mt++) {
                const float* s0 = sacc[mt][2 * ks];
                const float* s1 = sacc[mt][2 * ks + 1];
                ph[mt][0] = pack_h2(s0[0], s0[1]);
                ph[mt][1] = pack_h2(s0[2], s0[3]);
                ph[mt][2] = pack_h2(s1[0], s1[1]);
                ph[mt][3] = pack_h2(s1[2], s1[3]);
            }
            const uint32_t cidx = ks * 2 + (lane >> 4);
            #pragma unroll
            for (int g = 0; g < 4; g++) {
                const uint32_t row = g * 16 + lrow;
                const uint32_t ro = row * 128 + ((cidx ^ (row & 7)) << 4);
                uint32_t vv[4];
                ldsm_x4(vv, kvb + V_O + ro);
                #pragma unroll
                for (int mt = 0; mt < 2; mt++) {
                    mma_fp16(o[mt][g * 2 + 0], ph[mt], vv[0], vv[2]);
                    mma_fp16(o[mt][g * 2 + 1], ph[mt], vv[1], vv[3]);
                }
            }
        }
    }

    // ---- normalize + write ctx split hi/lo ----
    #pragma unroll
    for (int mt = 0; mt < 2; mt++) {
        const float inv0 = 1.0f / l_s[mt][0];
        const float inv1 = 1.0f / l_s[mt][1];
        const int r0 = row0[mt], r1 = row0[mt] + 8;
        #pragma unroll
        for (int f = 0; f < 8; f++) {
            const int col = h * 64 + f * 8 + (lane & 3) * 2;
            uint32_t h0, l0, h1, l1;
            split2(o[mt][f][0] * inv0, o[mt][f][1] * inv0, h0, l0);
            split2(o[mt][f][2] * inv1, o[mt][f][3] * inv1, h1, l1);
            *(uint32_t*)&g_ctxh[(size_t)r0 * DM + col] = h0;
            *(uint32_t*)&g_ctxl[(size_t)r0 * DM + col] = l0;
            *(uint32_t*)&g_ctxh[(size_t)r1 * DM + col] = h1;
            *(uint32_t*)&g_ctxl[(size_t)r1 * DM + col] = l1;
        }
    }
}

// ---------------------------------------------------------------------------
extern "C" void kernel_launch(void* const* d_in, const int* in_sizes, int n_in,
                              void* d_out, int out_size)
{
    const float* x  = (const float*)d_in[0];
    const float* Wq = (const float*)d_in[1];
    const float* Wk = (const float*)d_in[2];
    const float* Wv = (const float*)d_in[3];
    const float* Wo = (const float*)d_in[4];
    float* out = (float*)d_out;

    cudaFuncSetAttribute(gemm_qkv,
                         cudaFuncAttributeMaxDynamicSharedMemorySize, GEMM_SMEM_128);
    cudaFuncSetAttribute(gemm_out,
                         cudaFuncAttributeMaxDynamicSharedMemorySize, GEMM_SMEM_64);
    cudaFuncSetAttribute(attn_tc,
                         cudaFuncAttributeMaxDynamicSharedMemorySize, ATTN_SMEM);

    const int ntot4 = NX4 + 4 * NW4;
    split_all<<<(ntot4 + 255) / 256, 256>>>(x, Wq, Wk, Wv, Wo);

    gemm_qkv<<<dim3(S_LEN / 128, DM / 128, 3), 256, GEMM_SMEM_128>>>();

    attn_tc<<<dim3((S_LEN / 256) * NH), 256, ATTN_SMEM>>>();

    gemm_out<<<dim3(S_LEN / 128, DM / 64), 256, GEMM_SMEM_64>>>(out);
}

// round 14
// speedup vs baseline: 1.1462x; 1.1462x over previous
#include <cuda_runtime.h>
#include <cuda_bf16.h>
#include <cuda_fp16.h>
#include <cstdint>

#define S_LEN 4096
#define DM    768
#define NH    12
#define DK    64

// ---------------- scratch (device globals) ----------------
__device__ __nv_bfloat16 g_xh[S_LEN * DM],  g_xl[S_LEN * DM];
__device__ __nv_bfloat16 g_Wqh[DM * DM],    g_Wql[DM * DM];
__device__ __nv_bfloat16 g_Wkh[DM * DM],    g_Wkl[DM * DM];
__device__ __nv_bfloat16 g_Wvh[DM * DM],    g_Wvl[DM * DM];
__device__ __nv_bfloat16 g_Woh[DM * DM],    g_Wol[DM * DM];
__device__ __nv_bfloat16 g_Qh[S_LEN * DM],  g_Ql[S_LEN * DM];   // [s][hd]
__device__ __nv_bfloat16 g_Kh[S_LEN * DM],  g_Kl[S_LEN * DM];   // [s][hd]
__device__ __half        g_Vt[DM * S_LEN];                      // [hd][s], fp16
__device__ __nv_bfloat16 g_ctxh[S_LEN * DM], g_ctxl[S_LEN * DM];

// split-K partials: rows indexed (h, qb-16, r in 0..127) -> 12*16*128 = 24576
#define NSPLIT_ROWS (NH * 16 * 128)
__device__ float g_pm[2][NSPLIT_ROWS];
__device__ float g_pl[2][NSPLIT_ROWS];
__device__ float g_pO[2][NSPLIT_ROWS * DK];

// ---------------- helpers ----------------
__device__ __forceinline__ uint32_t smem_u32(const void* p) {
    uint32_t a;
    asm("{ .reg .u64 t; cvta.to.shared.u64 t, %1; cvt.u32.u64 %0, t; }"
        : "=r"(a) : "l"(p));
    return a;
}
__device__ __forceinline__ void ldsm_x4(uint32_t* r, uint32_t addr) {
    asm volatile("ldmatrix.sync.aligned.m8n8.x4.shared.b16 {%0,%1,%2,%3}, [%4];"
                 : "=r"(r[0]), "=r"(r[1]), "=r"(r[2]), "=r"(r[3]) : "r"(addr));
}
__device__ __forceinline__ void mma_bf16(float* d, const uint32_t* a,
                                         uint32_t b0, uint32_t b1) {
    asm volatile("mma.sync.aligned.m16n8k16.row.col.f32.bf16.bf16.f32 "
                 "{%0,%1,%2,%3}, {%4,%5,%6,%7}, {%8,%9}, {%0,%1,%2,%3};"
                 : "+f"(d[0]), "+f"(d[1]), "+f"(d[2]), "+f"(d[3])
                 : "r"(a[0]), "r"(a[1]), "r"(a[2]), "r"(a[3]), "r"(b0), "r"(b1));
}
__device__ __forceinline__ void mma_fp16(float* d, const uint32_t* a,
                                         uint32_t b0, uint32_t b1) {
    asm volatile("mma.sync.aligned.m16n8k16.row.col.f32.f16.f16.f32 "
                 "{%0,%1,%2,%3}, {%4,%5,%6,%7}, {%8,%9}, {%0,%1,%2,%3};"
                 : "+f"(d[0]), "+f"(d[1]), "+f"(d[2]), "+f"(d[3])
                 : "r"(a[0]), "r"(a[1]), "r"(a[2]), "r"(a[3]), "r"(b0), "r"(b1));
}
__device__ __forceinline__ void sts_v4(uint32_t addr, uint4 v) {
    asm volatile("st.shared.v4.b32 [%0], {%1, %2, %3, %4};"
                 :: "r"(addr), "r"(v.x), "r"(v.y), "r"(v.z), "r"(v.w) : "memory");
}
__device__ __forceinline__ void split2(float x, float y, uint32_t& hi, uint32_t& lo) {
    __nv_bfloat16 hx = __float2bfloat16(x), hy = __float2bfloat16(y);
    __nv_bfloat162 h2 = {hx, hy};
    hi = *(uint32_t*)&h2;
    __nv_bfloat162 l2 = {__float2bfloat16(x - __bfloat162float(hx)),
                         __float2bfloat16(y - __bfloat162float(hy))};
    lo = *(uint32_t*)&l2;
}
__device__ __forceinline__ uint32_t pack_h2(float x, float y) {
    __half2 h = __floats2half2_rn(x, y);
    return *(uint32_t*)&h;
}
__device__ __forceinline__ float round_h(float x) {
    return __half2float(__float2half_rn(x));
}
__device__ __forceinline__ void cp_async16(uint32_t dst, const void* src) {
    asm volatile("cp.async.cg.shared.global [%0], [%1], 16;"
                 :: "r"(dst), "l"(src));
}
#define CP_COMMIT() asm volatile("cp.async.commit_group;" ::: "memory")
#define CP_WAIT0()  asm volatile("cp.async.wait_group 0;" ::: "memory")

// ---------------- single fp32 -> bf16 hi/lo split pass for all 5 tensors ----
#define NX4 (S_LEN * DM / 4)
#define NW4 (DM * DM / 4)

__global__ __launch_bounds__(256)
void split_all(const float* __restrict__ x,  const float* __restrict__ Wq,
               const float* __restrict__ Wk, const float* __restrict__ Wv,
               const float* __restrict__ Wo)
{
    int i = blockIdx.x * blockDim.x + threadIdx.x;
    const float* in;
    __nv_bfloat16 *hi, *lo;
    int j = i;
    if (j < NX4)            { in = x;  hi = g_xh;  lo = g_xl;  }
    else if ((j -= NX4) < NW4)   { in = Wq; hi = g_Wqh; lo = g_Wql; }
    else if ((j -= NW4) < NW4)   { in = Wk; hi = g_Wkh; lo = g_Wkl; }
    else if ((j -= NW4) < NW4)   { in = Wv; hi = g_Wvh; lo = g_Wvl; }
    else if ((j -= NW4) < NW4)   { in = Wo; hi = g_Woh; lo = g_Wol; }
    else return;
    float4 v = ((const float4*)in)[j];
    uint32_t h0, l0, h1, l1;
    split2(v.x, v.y, h0, l0);
    split2(v.z, v.w, h1, l1);
    ((uint2*)hi)[j] = make_uint2(h0, h1);
    ((uint2*)lo)[j] = make_uint2(l0, l1);
}

// ===========================================================================
// bf16x3 GEMM body (unchanged from R12)
// ===========================================================================
#define ROWB      80
#define TILE_A    (128 * ROWB)

template<int OMODE, int BNR>
__device__ __forceinline__
void gemm_body(const __nv_bfloat16* __restrict__ Ah, const __nv_bfloat16* __restrict__ Al,
               const __nv_bfloat16* __restrict__ Bh, const __nv_bfloat16* __restrict__ Bl,
               float* __restrict__ C,
               __nv_bfloat16* __restrict__ Ch, __nv_bfloat16* __restrict__ Cl,
               __half* __restrict__ Cf16,
               int M, int N, int K, int bm, int bn, uint32_t sbase)
{
    constexpr int TILE_BB = BNR * ROWB;
    constexpr int BUF_B   = 2 * TILE_A + 2 * TILE_BB;
    constexpr int AHI = 0, ALO = TILE_A, BHI = 2 * TILE_A, BLO = 2 * TILE_A + TILE_BB;
    constexpr int NF = BNR / 16;
    constexpr int NCP = (1024 + BNR * 8) / 256;

    const int tid  = threadIdx.x;
    const int lane = tid & 31;
    const int warp = tid >> 5;
    const int m0 = (warp >> 1) * 32;
    const int n0 = (warp & 1) * (BNR / 2);

    float acc[2][NF][4];
    #pragma unroll
    for (int mt = 0; mt < 2; mt++)
        #pragma unroll
        for (int nf = 0; nf < NF; nf++)
            #pragma unroll
            for (int e = 0; e < 4; e++) acc[mt][nf][e] = 0.0f;

    const int nchunk = K / 32;

    auto issue = [&](int c) {
        const uint32_t buf = sbase + (uint32_t)(c & 1) * BUF_B;
        const int kc = c * 32;
        #pragma unroll
        for (int j = 0; j < NCP; j++) {
            const int idx = tid + j * 256;
            uint32_t dst;
            const __nv_bfloat16* src;
            if (idx < 512) {
                const int row = idx >> 2, ch = idx & 3;
                dst = buf + AHI + row * ROWB + ch * 16;
                src = &Ah[(size_t)(bm + row) * K + kc + ch * 8];
            } else if (idx < 1024) {
                const int r2 = idx - 512;
                const int row = r2 >> 2, ch = r2 & 3;
                dst = buf + ALO + row * ROWB + ch * 16;
                src = &Al[(size_t)(bm + row) * K + kc + ch * 8];
            } else if (idx < 1024 + BNR * 4) {
                const int r2 = idx - 1024;
                const int row = r2 >> 2, ch = r2 & 3;
                dst = buf + BHI + row * ROWB + ch * 16;
                src = &Bh[(size_t)(bn + row) * K + kc + ch * 8];
            } else {
                const int r2 = idx - (1024 + BNR * 4);
                const int row = r2 >> 2, ch = r2 & 3;
                dst = buf + BLO + row * ROWB + ch * 16;
                src = &Bl[(size_t)(bn + row) * K + kc + ch * 8];
            }
            cp_async16(dst, src);
        }
        CP_COMMIT();
    };

    issue(0);

    const uint32_t lrow = (lane & 15);
    const uint32_t koff = (lane >> 4) * 16;

    for (int c = 0; c < nchunk; ++c) {
        CP_WAIT0();
        __syncthreads();
        if (c + 1 < nchunk) issue(c + 1);

        const uint32_t buf = sbase + (uint32_t)(c & 1) * BUF_B;
        #pragma unroll
        for (int ks = 0; ks < 2; ks++) {
            const uint32_t kb = ks * 32 + koff;
            uint32_t ah[2][4], al[2][4];
            #pragma unroll
            for (int mt = 0; mt < 2; mt++) {
                const uint32_t ro = (uint32_t)(m0 + mt * 16 + lrow) * ROWB + kb;
                ldsm_x4(ah[mt], buf + AHI + ro);
                ldsm_x4(al[mt], buf + ALO + ro);
            }
            uint32_t bh[NF / 2][4], bl[NF / 2][4];
            #pragma unroll
            for (int g = 0; g < NF / 2; g++) {
                const uint32_t ro = (uint32_t)(n0 + g * 16 + lrow) * ROWB + kb;
                ldsm_x4(bh[g], buf + BHI + ro);
                ldsm_x4(bl[g], buf + BLO + ro);
            }
            #pragma unroll
            for (int mt = 0; mt < 2; mt++) {
                #pragma unroll
                for (int g = 0; g < NF / 2; g++) {
                    mma_bf16(acc[mt][g * 2 + 0], ah[mt], bh[g][0], bh[g][2]);
                    mma_bf16(acc[mt][g * 2 + 0], ah[mt], bl[g][0], bl[g][2]);
                    mma_bf16(acc[mt][g * 2 + 0], al[mt], bh[g][0], bh[g][2]);
                    mma_bf16(acc[mt][g * 2 + 1], ah[mt], bh[g][1], bh[g][3]);
                    mma_bf16(acc[mt][g * 2 + 1], ah[mt], bl[g][1], bl[g][3]);
                    mma_bf16(acc[mt][g * 2 + 1], al[mt], bh[g][1], bh[g][3]);
                }
            }
        }
        __syncthreads();
    }

    #pragma unroll
    for (int mt = 0; mt < 2; mt++) {
        const int row = bm + m0 + mt * 16 + (lane >> 2);
        #pragma unroll
        for (int nf = 0; nf < NF; nf++) {
            const int col = bn + n0 + nf * 8 + (lane & 3) * 2;
            if (OMODE == 0) {
                *(float2*)&C[(size_t)row * N + col] =
                    make_float2(acc[mt][nf][0], acc[mt][nf][1]);
                *(float2*)&C[(size_t)(row + 8) * N + col] =
                    make_float2(acc[mt][nf][2], acc[mt][nf][3]);
            } else if (OMODE == 1) {
                uint32_t h0, l0, h1, l1;
                split2(acc[mt][nf][0], acc[mt][nf][1], h0, l0);
                split2(acc[mt][nf][2], acc[mt][nf][3], h1, l1);
                *(uint32_t*)&Ch[(size_t)row * N + col]       = h0;
                *(uint32_t*)&Cl[(size_t)row * N + col]       = l0;
                *(uint32_t*)&Ch[(size_t)(row + 8) * N + col] = h1;
                *(uint32_t*)&Cl[(size_t)(row + 8) * N + col] = l1;
            } else {
                *(uint32_t*)&Cf16[(size_t)row * N + col] =
                    pack_h2(acc[mt][nf][0], acc[mt][nf][1]);
                *(uint32_t*)&Cf16[(size_t)(row + 8) * N + col] =
                    pack_h2(acc[mt][nf][2], acc[mt][nf][3]);
            }
        }
    }
}

#define GEMM_SMEM_128 (2 * (2 * TILE_A + 2 * 128 * ROWB))   // 81920
#define GEMM_SMEM_64  (2 * (2 * TILE_A + 2 * 64 * ROWB))    // 61440

__global__ __launch_bounds__(256, 2)
void gemm_qkv()
{
    extern __shared__ __align__(128) char dynsm[];
    const uint32_t sbase = smem_u32(dynsm);
    const int z = blockIdx.z;

    if (z == 0) {
        gemm_body<1, 128>(g_xh, g_xl, g_Wqh, g_Wql, nullptr, g_Qh, g_Ql, nullptr,
                          S_LEN, DM, DM, blockIdx.x * 128, blockIdx.y * 128, sbase);
    } else if (z == 1) {
        gemm_body<1, 128>(g_xh, g_xl, g_Wkh, g_Wkl, nullptr, g_Kh, g_Kl, nullptr,
                          S_LEN, DM, DM, blockIdx.x * 128, blockIdx.y * 128, sbase);
    } else {
        gemm_body<2, 128>(g_Wvh, g_Wvl, g_xh, g_xl, nullptr, nullptr, nullptr, g_Vt,
                          DM, S_LEN, DM, blockIdx.y * 128, blockIdx.x * 128, sbase);
    }
}

__global__ __launch_bounds__(256, 2)
void gemm_out(float* __restrict__ out)
{
    extern __shared__ __align__(128) char dynsm[];
    const uint32_t sbase = smem_u32(dynsm);
    gemm_body<0, 64>(g_ctxh, g_ctxl, g_Woh, g_Wol, out, nullptr, nullptr, nullptr,
                     S_LEN, DM, DM, blockIdx.x * 128, blockIdx.y * 64, sbase);
}

// ===========================================================================
// Attention (R12 inner loop) with split-K over heavy causal CTAs.
// qb 0..15: one CTA (tiles [0, 2qb+2)).  qb 16..31: two CTAs, key halves
// [0, qb+1) and [qb+1, 2qb+2), emitting fp32 partials merged by attn_merge.
// Jobs dispatched in size-descending (LPT) order via bucket search.
// ===========================================================================
#define AROWB 144
#define AQH   0
#define AQL   (128 * AROWB)
#define AKV   (2 * 128 * AROWB)          // 36864
#define KVSTG 24576                      // Kh 8K + Kl 8K + V 8K
#define KH_O  0
#define KL_O  8192
#define V_O   16384
#define ATTN_SMEM (AKV + 2 * KVSTG)      // 86016
#define ATTN_JOBS 576

__global__ __launch_bounds__(256, 2)
void attn_tc()
{
    extern __shared__ __align__(128) char dynbuf[];
    const uint32_t sb = smem_u32(dynbuf);

    const int tid  = threadIdx.x;
    const int lane = tid & 31;
    const int warp = tid >> 5;
    const int wr   = warp * 16;

    // ---- LPT job decode: buckets by size s = #tiles, descending ----
    // size s: split jobs (24) exist for s in [17,32] (qb = s-1);
    //         light jobs (12) exist for even s in [2,32] (qb = s/2-1).
    int rem = blockIdx.x;
    int qb = 0, t0 = 0, t1 = 2, h = 0, part = 0, is_light = 1;
    #pragma unroll 1
    for (int s = 32; s >= 2; --s) {
        const int nsplit = (s >= 17) ? 24 : 0;
        const int nlight = ((s & 1) == 0) ? 12 : 0;
        if (rem < nsplit + nlight) {
            if (rem < nsplit) {
                qb = s - 1; part = rem / 12; h = rem % 12;
                t0 = part * (qb + 1); t1 = t0 + (qb + 1);
                is_light = 0;
            } else {
                const int i2 = rem - nsplit;
                qb = s / 2 - 1; h = i2;
                t0 = 0; t1 = 2 * qb + 2;
                is_light = 1; part = 0;
            }
            break;
        }
        rem -= nsplit + nlight;
    }
    const int q0 = qb * 128;

    // ---- load Q tile (hi/lo) ----
    {
        const int gr = tid >> 3;
        const int gc = tid & 7;
        #pragma unroll
        for (int i = 0; i < 4; i++) {
            const int r = gr + i * 32;
            const uint32_t soff = (uint32_t)r * AROWB + gc * 16;
            uint4 vh = *(const uint4*)&g_Qh[(size_t)(q0 + r) * DM + h * 64 + gc * 8];
            uint4 vl = *(const uint4*)&g_Ql[(size_t)(q0 + r) * DM + h * 64 + gc * 8];
            sts_v4(sb + AQH + soff, vh);
            sts_v4(sb + AQL + soff, vl);
        }
    }

    auto issue_kv = [&](int t) {
        const uint32_t kvb = sb + AKV + (uint32_t)(t & 1) * KVSTG;
        const int k0 = t * 64;
        #pragma unroll
        for (int j = 0; j < 6; j++) {
            const int idx = tid + j * 256;
            const int arr = idx >> 9;
            const int rem2 = idx & 511;
            const int row = rem2 >> 3;
            const int c   = rem2 & 7;
            const uint32_t dst = kvb + (uint32_t)arr * 8192 + row * 128 +
                                 ((uint32_t)(c ^ (row & 7)) << 4);
            const void* src;
            if (arr == 0)      src = &g_Kh[(size_t)(k0 + row) * DM + h * 64 + c * 8];
            else if (arr == 1) src = &g_Kl[(size_t)(k0 + row) * DM + h * 64 + c * 8];
            else               src = &g_Vt[(size_t)(h * 64 + row) * S_LEN + k0 + c * 8];
            cp_async16(dst, src);
        }
        CP_COMMIT();
    };

    issue_kv(t0);

    float o[8][4];
    #pragma unroll
    for (int f = 0; f < 8; f++)
        #pragma unroll
        for (int e = 0; e < 4; e++) o[f][e] = 0.0f;
    float m_s[2] = {-1e30f, -1e30f};
    float l_s[2] = {0.0f, 0.0f};

    const int row0 = q0 + wr + (lane >> 2);
    const int row1 = row0 + 8;
    const uint32_t lrow = (lane & 15);
    const uint32_t koff = (lane >> 4) * 16;

    for (int t = t0; t < t1; ++t) {
        const int k0 = t * 64;
        CP_WAIT0();
        __syncthreads();
        if (t + 1 < t1) issue_kv(t + 1);

        const uint32_t kvb = sb + AKV + (uint32_t)(t & 1) * KVSTG;

        float sacc[8][4];
        #pragma unroll
        for (int f = 0; f < 8; f++)
            #pragma unroll
            for (int e = 0; e < 4; e++) sacc[f][e] = 0.0f;

        #pragma unroll
        for (int ks = 0; ks < 4; ks++) {
            uint32_t qh[4], ql[4];
            const uint32_t qoff = (uint32_t)(wr + lrow) * AROWB + ks * 32 + koff;
            ldsm_x4(qh, sb + AQH + qoff);
            ldsm_x4(ql, sb + AQL + qoff);
            const uint32_t cidx = ks * 2 + (lane >> 4);
            #pragma unroll
            for (int g = 0; g < 4; g++) {
                const uint32_t row = g * 16 + lrow;
                const uint32_t ro = row * 128 + ((cidx ^ (row & 7)) << 4);
                uint32_t kh[4], kl[4];
                ldsm_x4(kh, kvb + KH_O + ro);
                ldsm_x4(kl, kvb + KL_O + ro);
                mma_bf16(sacc[g * 2 + 0], qh, kh[0], kh[2]);
                mma_bf16(sacc[g * 2 + 0], qh, kl[0], kl[2]);
                mma_bf16(sacc[g * 2 + 0], ql, kh[0], kh[2]);
                mma_bf16(sacc[g * 2 + 1], qh, kh[1], kh[3]);
                mma_bf16(sacc[g * 2 + 1], qh, kl[1], kl[3]);
                mma_bf16(sacc[g * 2 + 1], ql, kh[1], kh[3]);
            }
        }

        const float scale = 0.125f;
        if (t >= 2 * qb) {
            #pragma unroll
            for (int f = 0; f < 8; f++) {
                const int cb = k0 + f * 8 + (lane & 3) * 2;
                sacc[f][0] = (cb     > row0) ? -1e30f : sacc[f][0] * scale;
                sacc[f][1] = (cb + 1 > row0) ? -1e30f : sacc[f][1] * scale;
                sacc[f][2] = (cb     > row1) ? -1e30f : sacc[f][2] * scale;
                sacc[f][3] = (cb + 1 > row1) ? -1e30f : sacc[f][3] * scale;
            }
        } else {
            #pragma unroll
            for (int f = 0; f < 8; f++)
                #pragma unroll
                for (int e = 0; e < 4; e++) sacc[f][e] *= scale;
        }

        float rm0 = -1e30f, rm1 = -1e30f;
        #pragma unroll
        for (int f = 0; f < 8; f++) {
            rm0 = fmaxf(rm0, fmaxf(sacc[f][0], sacc[f][1]));
            rm1 = fmaxf(rm1, fmaxf(sacc[f][2], sacc[f][3]));
        }
        #pragma unroll
        for (int off = 1; off < 4; off <<= 1) {
            rm0 = fmaxf(rm0, __shfl_xor_sync(0xffffffffu, rm0, off));
            rm1 = fmaxf(rm1, __shfl_xor_sync(0xffffffffu, rm1, off));
        }
        const float mn0 = fmaxf(m_s[0], rm0);
        const float mn1 = fmaxf(m_s[1], rm1);
        const float al0 = __expf(m_s[0] - mn0);
        const float al1 = __expf(m_s[1] - mn1);
        float rs0 = 0.0f, rs1 = 0.0f;
        #pragma unroll
        for (int f = 0; f < 8; f++) {
            sacc[f][0] = round_h(__expf(sacc[f][0] - mn0));
            sacc[f][1] = round_h(__expf(sacc[f][1] - mn0));
            sacc[f][2] = round_h(__expf(sacc[f][2] - mn1));
            sacc[f][3] = round_h(__expf(sacc[f][3] - mn1));
            rs0 += sacc[f][0] + sacc[f][1];
            rs1 += sacc[f][2] + sacc[f][3];
        }
        #pragma unroll
        for (int off = 1; off < 4; off <<= 1) {
            rs0 += __shfl_xor_sync(0xffffffffu, rs0, off);
            rs1 += __shfl_xor_sync(0xffffffffu, rs1, off);
        }
        l_s[0] = l_s[0] * al0 + rs0;
        l_s[1] = l_s[1] * al1 + rs1;
        m_s[0] = mn0;
        m_s[1] = mn1;
        #pragma unroll
        for (int f = 0; f < 8; f++) {
            o[f][0] *= al0; o[f][1] *= al0;
            o[f][2] *= al1; o[f][3] *= al1;
        }

        #pragma unroll
        for (int ks = 0; ks < 4; ks++) {
            const float* s0 = sacc[2 * ks];
            const float* s1 = sacc[2 * ks + 1];
            uint32_t ph[4];
            ph[0] = pack_h2(s0[0], s0[1]);
            ph[1] = pack_h2(s0[2], s0[3]);
            ph[2] = pack_h2(s1[0], s1[1]);
            ph[3] = pack_h2(s1[2], s1[3]);
            const uint32_t cidx = ks * 2 + (lane >> 4);
            #pragma unroll
            for (int g = 0; g < 4; g++) {
                const uint32_t row = g * 16 + lrow;
                const uint32_t ro = row * 128 + ((cidx ^ (row & 7)) << 4);
                uint32_t vv[4];
                ldsm_x4(vv, kvb + V_O + ro);
                mma_fp16(o[g * 2 + 0], ph, vv[0], vv[2]);
                mma_fp16(o[g * 2 + 1], ph, vv[1], vv[3]);
            }
        }
    }

    if (is_light) {
        const float inv0 = 1.0f / l_s[0];
        const float inv1 = 1.0f / l_s[1];
        #pragma unroll
        for (int f = 0; f < 8; f++) {
            const int col = h * 64 + f * 8 + (lane & 3) * 2;
            uint32_t h0, l0, h1, l1;
            split2(o[f][0] * inv0, o[f][1] * inv0, h0, l0);
            split2(o[f][2] * inv1, o[f][3] * inv1, h1, l1);
            *(uint32_t*)&g_ctxh[(size_t)row0 * DM + col] = h0;
            *(uint32_t*)&g_ctxl[(size_t)row0 * DM + col] = l0;
            *(uint32_t*)&g_ctxh[(size_t)row1 * DM + col] = h1;
            *(uint32_t*)&g_ctxl[(size_t)row1 * DM + col] = l1;
        }
    } else {
        // write fp32 partials: rid = (h*16 + (qb-16))*128 + local row
        const int base = (h * 16 + (qb - 16)) * 128;
        const int r0 = base + (row0 - q0);
        const int r1 = base + (row1 - q0);
        g_pm[part][r0] = m_s[0];
        g_pl[part][r0] = l_s[0];
        g_pm[part][r1] = m_s[1];
        g_pl[part][r1] = l_s[1];
        #pragma unroll
        for (int f = 0; f < 8; f++) {
            const int d = f * 8 + (lane & 3) * 2;
            *(float2*)&g_pO[part][(size_t)r0 * DK + d] = make_float2(o[f][0], o[f][1]);
            *(float2*)&g_pO[part][(size_t)r1 * DK + d] = make_float2(o[f][2], o[f][3]);
        }
    }
}

// ---- merge split-K partials into ctx (exact online-softmax merge) ----
__global__ __launch_bounds__(256)
void attn_merge()
{
    const int tid = blockIdx.x * 256 + threadIdx.x;   // 0 .. NSPLIT_ROWS*32-1
    if (tid >= NSPLIT_ROWS * 32) return;
    const int rid = tid >> 5;
    const int d   = (tid & 31) * 2;

    const float m0 = g_pm[0][rid], m1 = g_pm[1][rid];
    const float M  = fmaxf(m0, m1);
    const float w0 = __expf(m0 - M);
    const float w1 = __expf(m1 - M);
    const float inv = 1.0f / (w0 * g_pl[0][rid] + w1 * g_pl[1][rid]);

    const float2 a0 = *(const float2*)&g_pO[0][(size_t)rid * DK + d];
    const float2 a1 = *(const float2*)&g_pO[1][(size_t)rid * DK + d];
    const float va = (w0 * a0.x + w1 * a1.x) * inv;
    const float vb = (w0 * a0.y + w1 * a1.y) * inv;

    const int h    = rid / 2048;
    const int qb16 = (rid >> 7) & 15;
    const int r    = rid & 127;
    const int grow = (16 + qb16) * 128 + r;
    const int col  = h * 64 + d;

    uint32_t hi, lo;
    split2(va, vb, hi, lo);
    *(uint32_t*)&g_ctxh[(size_t)grow * DM + col] = hi;
    *(uint32_t*)&g_ctxl[(size_t)grow * DM + col] = lo;
}

// ---------------------------------------------------------------------------
extern "C" void kernel_launch(void* const* d_in, const int* in_sizes, int n_in,
                              void* d_out, int out_size)
{
    const float* x  = (const float*)d_in[0];
    const float* Wq = (const float*)d_in[1];
    const float* Wk = (const float*)d_in[2];
    const float* Wv = (const float*)d_in[3];
    const float* Wo = (const float*)d_in[4];
    float* out = (float*)d_out;

    cudaFuncSetAttribute(gemm_qkv,
                         cudaFuncAttributeMaxDynamicSharedMemorySize, GEMM_SMEM_128);
    cudaFuncSetAttribute(gemm_out,
                         cudaFuncAttributeMaxDynamicSharedMemorySize, GEMM_SMEM_64);
    cudaFuncSetAttribute(attn_tc,
                         cudaFuncAttributeMaxDynamicSharedMemorySize, ATTN_SMEM);

    const int ntot4 = NX4 + 4 * NW4;
    split_all<<<(ntot4 + 255) / 256, 256>>>(x, Wq, Wk, Wv, Wo);

    gemm_qkv<<<dim3(S_LEN / 128, DM / 128, 3), 256, GEMM_SMEM_128>>>();

    attn_tc<<<dim3(ATTN_JOBS), 256, ATTN_SMEM>>>();
    attn_merge<<<(NSPLIT_ROWS * 32 + 255) / 256, 256>>>();

    gemm_out<<<dim3(S_LEN / 128, DM / 64), 256, GEMM_SMEM_64>>>(out);
}

// round 15
// speedup vs baseline: 1.1657x; 1.0170x over previous
#include <cuda_runtime.h>
#include <cuda_bf16.h>
#include <cuda_fp16.h>
#include <cstdint>

#define S_LEN 4096
#define DM    768
#define NH    12
#define DK    64

// ---------------- scratch (device globals) ----------------
__device__ __nv_bfloat16 g_xh[S_LEN * DM],  g_xl[S_LEN * DM];
__device__ __nv_bfloat16 g_Wqh[DM * DM],    g_Wql[DM * DM];
__device__ __nv_bfloat16 g_Wkh[DM * DM],    g_Wkl[DM * DM];
__device__ __nv_bfloat16 g_Wvh[DM * DM],    g_Wvl[DM * DM];
__device__ __nv_bfloat16 g_Woh[DM * DM],    g_Wol[DM * DM];
__device__ __nv_bfloat16 g_Qh[S_LEN * DM],  g_Ql[S_LEN * DM];   // [s][hd]
__device__ __nv_bfloat16 g_Kh[S_LEN * DM],  g_Kl[S_LEN * DM];   // [s][hd]
__device__ __half        g_Vt[DM * S_LEN];                      // [hd][s], fp16
__device__ __nv_bfloat16 g_ctxh[S_LEN * DM], g_ctxl[S_LEN * DM];

// split-K partials: rows indexed (h, qb-12 in 0..19, r in 0..127)
#define NSPLIT_ROWS (NH * 20 * 128)      // 30720
__device__ float g_pm[3][NSPLIT_ROWS];
__device__ float g_pl[3][NSPLIT_ROWS];
__device__ float g_pO[3][NSPLIT_ROWS * DK];

// ---- LPT job table: 60 job types (size-descending), x12 heads = 720 jobs.
// part 255 = light (normalize inline); else partial slot 0..2.
#define NJOBT 60
__constant__ uint8_t c_qb[NJOBT] = {
    23,23,11, 22,22, 21,21,31,31,10, 20,20,30,30,
    19,19,29,29,29,31,30,28,28, 9, 18,18,27,27,
    17,17,26,26,26,28,27,25,25, 8, 16,16,24,24,
    15,15,25,24, 7, 14,14, 13,13, 6, 12,12,
     5, 4, 3, 2, 1, 0 };
__constant__ uint8_t c_t0[NJOBT] = {
     0,24, 0,  0,23,  0,22, 0,22, 0,  0,21, 0,21,
     0,20, 0,20,40,44,42, 0,20, 0,  0,19, 0,19,
     0,18, 0,18,36,40,38, 0,18, 0,  0,17, 0,17,
     0,16,36,34, 0,  0,15,  0,14, 0,  0,13,
     0, 0, 0, 0, 0, 0 };
__constant__ uint8_t c_t1[NJOBT] = {
    24,48,24, 23,46, 22,44,22,44,22, 21,42,21,42,
    20,40,20,40,60,64,62,20,40,20, 19,38,19,38,
    18,36,18,36,54,58,56,18,36,18, 17,34,17,34,
    16,32,52,50,16, 15,30, 14,28,14, 13,26,
    12,10, 8, 6, 4, 2 };
__constant__ uint8_t c_pt[NJOBT] = {
     0,1,255, 0,1, 0,1,0,1,255, 0,1,0,1,
     0,1,0,1,2,2,2,0,1,255, 0,1,0,1,
     0,1,0,1,2,2,2,0,1,255, 0,1,0,1,
     0,1,2,2,255, 0,1, 0,1,255, 0,1,
     255,255,255,255,255,255 };
#define ATTN_JOBS (NJOBT * NH)           // 720

// ---------------- helpers ----------------
__device__ __forceinline__ uint32_t smem_u32(const void* p) {
    uint32_t a;
    asm("{ .reg .u64 t; cvta.to.shared.u64 t, %1; cvt.u32.u64 %0, t; }"
        : "=r"(a) : "l"(p));
    return a;
}
__device__ __forceinline__ void ldsm_x4(uint32_t* r, uint32_t addr) {
    asm volatile("ldmatrix.sync.aligned.m8n8.x4.shared.b16 {%0,%1,%2,%3}, [%4];"
                 : "=r"(r[0]), "=r"(r[1]), "=r"(r[2]), "=r"(r[3]) : "r"(addr));
}
__device__ __forceinline__ void mma_bf16(float* d, const uint32_t* a,
                                         uint32_t b0, uint32_t b1) {
    asm volatile("mma.sync.aligned.m16n8k16.row.col.f32.bf16.bf16.f32 "
                 "{%0,%1,%2,%3}, {%4,%5,%6,%7}, {%8,%9}, {%0,%1,%2,%3};"
                 : "+f"(d[0]), "+f"(d[1]), "+f"(d[2]), "+f"(d[3])
                 : "r"(a[0]), "r"(a[1]), "r"(a[2]), "r"(a[3]), "r"(b0), "r"(b1));
}
__device__ __forceinline__ void mma_fp16(float* d, const uint32_t* a,
                                         uint32_t b0, uint32_t b1) {
    asm volatile("mma.sync.aligned.m16n8k16.row.col.f32.f16.f16.f32 "
                 "{%0,%1,%2,%3}, {%4,%5,%6,%7}, {%8,%9}, {%0,%1,%2,%3};"
                 : "+f"(d[0]), "+f"(d[1]), "+f"(d[2]), "+f"(d[3])
                 : "r"(a[0]), "r"(a[1]), "r"(a[2]), "r"(a[3]), "r"(b0), "r"(b1));
}
__device__ __forceinline__ void sts_v4(uint32_t addr, uint4 v) {
    asm volatile("st.shared.v4.b32 [%0], {%1, %2, %3, %4};"
                 :: "r"(addr), "r"(v.x), "r"(v.y), "r"(v.z), "r"(v.w) : "memory");
}
__device__ __forceinline__ void split2(float x, float y, uint32_t& hi, uint32_t& lo) {
    __nv_bfloat16 hx = __float2bfloat16(x), hy = __float2bfloat16(y);
    __nv_bfloat162 h2 = {hx, hy};
    hi = *(uint32_t*)&h2;
    __nv_bfloat162 l2 = {__float2bfloat16(x - __bfloat162float(hx)),
                         __float2bfloat16(y - __bfloat162float(hy))};
    lo = *(uint32_t*)&l2;
}
__device__ __forceinline__ uint32_t pack_h2(float x, float y) {
    __half2 h = __floats2half2_rn(x, y);
    return *(uint32_t*)&h;
}
__device__ __forceinline__ float round_h(float x) {
    return __half2float(__float2half_rn(x));
}
__device__ __forceinline__ void cp_async16(uint32_t dst, const void* src) {
    asm volatile("cp.async.cg.shared.global [%0], [%1], 16;"
                 :: "r"(dst), "l"(src));
}
#define CP_COMMIT() asm volatile("cp.async.commit_group;" ::: "memory")
#define CP_WAIT0()  asm volatile("cp.async.wait_group 0;" ::: "memory")

// ---------------- single fp32 -> bf16 hi/lo split pass ----------------
#define NX4 (S_LEN * DM / 4)
#define NW4 (DM * DM / 4)

__global__ __launch_bounds__(256)
void split_all(const float* __restrict__ x,  const float* __restrict__ Wq,
               const float* __restrict__ Wk, const float* __restrict__ Wv,
               const float* __restrict__ Wo)
{
    int i = blockIdx.x * blockDim.x + threadIdx.x;
    const float* in;
    __nv_bfloat16 *hi, *lo;
    int j = i;
    if (j < NX4)            { in = x;  hi = g_xh;  lo = g_xl;  }
    else if ((j -= NX4) < NW4)   { in = Wq; hi = g_Wqh; lo = g_Wql; }
    else if ((j -= NW4) < NW4)   { in = Wk; hi = g_Wkh; lo = g_Wkl; }
    else if ((j -= NW4) < NW4)   { in = Wv; hi = g_Wvh; lo = g_Wvl; }
    else if ((j -= NW4) < NW4)   { in = Wo; hi = g_Woh; lo = g_Wol; }
    else return;
    float4 v = ((const float4*)in)[j];
    uint32_t h0, l0, h1, l1;
    split2(v.x, v.y, h0, l0);
    split2(v.z, v.w, h1, l1);
    ((uint2*)hi)[j] = make_uint2(h0, h1);
    ((uint2*)lo)[j] = make_uint2(l0, l1);
}

// ===========================================================================
// bf16x3 GEMM body (R12 configuration, BNR templated: 128 / 96 / 64)
// ===========================================================================
#define ROWB      80
#define TILE_A    (128 * ROWB)

template<int OMODE, int BNR>
__device__ __forceinline__
void gemm_body(const __nv_bfloat16* __restrict__ Ah, const __nv_bfloat16* __restrict__ Al,
               const __nv_bfloat16* __restrict__ Bh, const __nv_bfloat16* __restrict__ Bl,
               float* __restrict__ C,
               __nv_bfloat16* __restrict__ Ch, __nv_bfloat16* __restrict__ Cl,
               __half* __restrict__ Cf16,
               int M, int N, int K, int bm, int bn, uint32_t sbase)
{
    constexpr int TILE_BB = BNR * ROWB;
    constexpr int BUF_B   = 2 * TILE_A + 2 * TILE_BB;
    constexpr int AHI = 0, ALO = TILE_A, BHI = 2 * TILE_A, BLO = 2 * TILE_A + TILE_BB;
    constexpr int NF = BNR / 16;
    constexpr int NCP = (1024 + BNR * 8) / 256;

    const int tid  = threadIdx.x;
    const int lane = tid & 31;
    const int warp = tid >> 5;
    const int m0 = (warp >> 1) * 32;
    const int n0 = (warp & 1) * (BNR / 2);

    float acc[2][NF][4];
    #pragma unroll
    for (int mt = 0; mt < 2; mt++)
        #pragma unroll
        for (int nf = 0; nf < NF; nf++)
            #pragma unroll
            for (int e = 0; e < 4; e++) acc[mt][nf][e] = 0.0f;

    const int nchunk = K / 32;

    auto issue = [&](int c) {
        const uint32_t buf = sbase + (uint32_t)(c & 1) * BUF_B;
        const int kc = c * 32;
        #pragma unroll
        for (int j = 0; j < NCP; j++) {
            const int idx = tid + j * 256;
            uint32_t dst;
            const __nv_bfloat16* src;
            if (idx < 512) {
                const int row = idx >> 2, ch = idx & 3;
                dst = buf + AHI + row * ROWB + ch * 16;
                src = &Ah[(size_t)(bm + row) * K + kc + ch * 8];
            } else if (idx < 1024) {
                const int r2 = idx - 512;
                const int row = r2 >> 2, ch = r2 & 3;
                dst = buf + ALO + row * ROWB + ch * 16;
                src = &Al[(size_t)(bm + row) * K + kc + ch * 8];
            } else if (idx < 1024 + BNR * 4) {
                const int r2 = idx - 1024;
                const int row = r2 >> 2, ch = r2 & 3;
                dst = buf + BHI + row * ROWB + ch * 16;
                src = &Bh[(size_t)(bn + row) * K + kc + ch * 8];
            } else {
                const int r2 = idx - (1024 + BNR * 4);
                const int row = r2 >> 2, ch = r2 & 3;
                dst = buf + BLO + row * ROWB + ch * 16;
                src = &Bl[(size_t)(bn + row) * K + kc + ch * 8];
            }
            cp_async16(dst, src);
        }
        CP_COMMIT();
    };

    issue(0);

    const uint32_t lrow = (lane & 15);
    const uint32_t koff = (lane >> 4) * 16;

    for (int c = 0; c < nchunk; ++c) {
        CP_WAIT0();
        __syncthreads();
        if (c + 1 < nchunk) issue(c + 1);

        const uint32_t buf = sbase + (uint32_t)(c & 1) * BUF_B;
        #pragma unroll
        for (int ks = 0; ks < 2; ks++) {
            const uint32_t kb = ks * 32 + koff;
            uint32_t ah[2][4], al[2][4];
            #pragma unroll
            for (int mt = 0; mt < 2; mt++) {
                const uint32_t ro = (uint32_t)(m0 + mt * 16 + lrow) * ROWB + kb;
                ldsm_x4(ah[mt], buf + AHI + ro);
                ldsm_x4(al[mt], buf + ALO + ro);
            }
            uint32_t bh[NF / 2][4], bl[NF / 2][4];
            #pragma unroll
            for (int g = 0; g < NF / 2; g++) {
                const uint32_t ro = (uint32_t)(n0 + g * 16 + lrow) * ROWB + kb;
                ldsm_x4(bh[g], buf + BHI + ro);
                ldsm_x4(bl[g], buf + BLO + ro);
            }
            #pragma unroll
            for (int mt = 0; mt < 2; mt++) {
                #pragma unroll
                for (int g = 0; g < NF / 2; g++) {
                    mma_bf16(acc[mt][g * 2 + 0], ah[mt], bh[g][0], bh[g][2]);
                    mma_bf16(acc[mt][g * 2 + 0], ah[mt], bl[g][0], bl[g][2]);
                    mma_bf16(acc[mt][g * 2 + 0], al[mt], bh[g][0], bh[g][2]);
                    mma_bf16(acc[mt][g * 2 + 1], ah[mt], bh[g][1], bh[g][3]);
                    mma_bf16(acc[mt][g * 2 + 1], ah[mt], bl[g][1], bl[g][3]);
                    mma_bf16(acc[mt][g * 2 + 1], al[mt], bh[g][1], bh[g][3]);
                }
            }
        }
        __syncthreads();
    }

    #pragma unroll
    for (int mt = 0; mt < 2; mt++) {
        const int row = bm + m0 + mt * 16 + (lane >> 2);
        #pragma unroll
        for (int nf = 0; nf < NF; nf++) {
            const int col = bn + n0 + nf * 8 + (lane & 3) * 2;
            if (OMODE == 0) {
                *(float2*)&C[(size_t)row * N + col] =
                    make_float2(acc[mt][nf][0], acc[mt][nf][1]);
                *(float2*)&C[(size_t)(row + 8) * N + col] =
                    make_float2(acc[mt][nf][2], acc[mt][nf][3]);
            } else if (OMODE == 1) {
                uint32_t h0, l0, h1, l1;
                split2(acc[mt][nf][0], acc[mt][nf][1], h0, l0);
                split2(acc[mt][nf][2], acc[mt][nf][3], h1, l1);
                *(uint32_t*)&Ch[(size_t)row * N + col]       = h0;
                *(uint32_t*)&Cl[(size_t)row * N + col]       = l0;
                *(uint32_t*)&Ch[(size_t)(row + 8) * N + col] = h1;
                *(uint32_t*)&Cl[(size_t)(row + 8) * N + col] = l1;
            } else {
                *(uint32_t*)&Cf16[(size_t)row * N + col] =
                    pack_h2(acc[mt][nf][0], acc[mt][nf][1]);
                *(uint32_t*)&Cf16[(size_t)(row + 8) * N + col] =
                    pack_h2(acc[mt][nf][2], acc[mt][nf][3]);
            }
        }
    }
}

#define GEMM_SMEM_128 (2 * (2 * TILE_A + 2 * 128 * ROWB))   // 81920
#define GEMM_SMEM_96  (2 * (2 * TILE_A + 2 * 96 * ROWB))    // 71680

__global__ __launch_bounds__(256, 2)
void gemm_qkv()
{
    extern __shared__ __align__(128) char dynsm[];
    const uint32_t sbase = smem_u32(dynsm);
    const int z = blockIdx.z;

    if (z == 0) {
        gemm_body<1, 128>(g_xh, g_xl, g_Wqh, g_Wql, nullptr, g_Qh, g_Ql, nullptr,
                          S_LEN, DM, DM, blockIdx.x * 128, blockIdx.y * 128, sbase);
    } else if (z == 1) {
        gemm_body<1, 128>(g_xh, g_xl, g_Wkh, g_Wkl, nullptr, g_Kh, g_Kl, nullptr,
                          S_LEN, DM, DM, blockIdx.x * 128, blockIdx.y * 128, sbase);
    } else {
        gemm_body<2, 128>(g_Wvh, g_Wvl, g_xh, g_xl, nullptr, nullptr, nullptr, g_Vt,
                          DM, S_LEN, DM, blockIdx.y * 128, blockIdx.x * 128, sbase);
    }
}

// Output projection: 128x96 tiles -> 256 CTAs = single wave at 2 CTA/SM
__global__ __launch_bounds__(256, 2)
void gemm_out(float* __restrict__ out)
{
    extern __shared__ __align__(128) char dynsm[];
    const uint32_t sbase = smem_u32(dynsm);
    gemm_body<0, 96>(g_ctxh, g_ctxl, g_Woh, g_Wol, out, nullptr, nullptr, nullptr,
                     S_LEN, DM, DM, blockIdx.x * 128, blockIdx.y * 96, sbase);
}

// ===========================================================================
// Attention (R12 inner loop) with fine split-K (jobs <= 24 tiles) + LPT table.
// ===========================================================================
#define AROWB 144
#define AQH   0
#define AQL   (128 * AROWB)
#define AKV   (2 * 128 * AROWB)          // 36864
#define KVSTG 24576
#define KH_O  0
#define KL_O  8192
#define V_O   16384
#define ATTN_SMEM (AKV + 2 * KVSTG)      // 86016

__global__ __launch_bounds__(256, 2)
void attn_tc()
{
    extern __shared__ __align__(128) char dynbuf[];
    const uint32_t sb = smem_u32(dynbuf);

    const int tid  = threadIdx.x;
    const int lane = tid & 31;
    const int warp = tid >> 5;
    const int wr   = warp * 16;

    const int type = blockIdx.x / NH;
    const int h    = blockIdx.x % NH;
    const int qb   = c_qb[type];
    const int t0   = c_t0[type];
    const int t1   = c_t1[type];
    const int part = c_pt[type];
    const int q0   = qb * 128;

    // ---- load Q tile (hi/lo) ----
    {
        const int gr = tid >> 3;
        const int gc = tid & 7;
        #pragma unroll
        for (int i = 0; i < 4; i++) {
            const int r = gr + i * 32;
            const uint32_t soff = (uint32_t)r * AROWB + gc * 16;
            uint4 vh = *(const uint4*)&g_Qh[(size_t)(q0 + r) * DM + h * 64 + gc * 8];
            uint4 vl = *(const uint4*)&g_Ql[(size_t)(q0 + r) * DM + h * 64 + gc * 8];
            sts_v4(sb + AQH + soff, vh);
            sts_v4(sb + AQL + soff, vl);
        }
    }

    auto issue_kv = [&](int t) {
        const uint32_t kvb = sb + AKV + (uint32_t)(t & 1) * KVSTG;
        const int k0 = t * 64;
        #pragma unroll
        for (int j = 0; j < 6; j++) {
            const int idx = tid + j * 256;
            const int arr = idx >> 9;
            const int rem2 = idx & 511;
            const int row = rem2 >> 3;
            const int c   = rem2 & 7;
            const uint32_t dst = kvb + (uint32_t)arr * 8192 + row * 128 +
                                 ((uint32_t)(c ^ (row & 7)) << 4);
            const void* src;
            if (arr == 0)      src = &g_Kh[(size_t)(k0 + row) * DM + h * 64 + c * 8];
            else if (arr == 1) src = &g_Kl[(size_t)(k0 + row) * DM + h * 64 + c * 8];
            else               src = &g_Vt[(size_t)(h * 64 + row) * S_LEN + k0 + c * 8];
            cp_async16(dst, src);
        }
        CP_COMMIT();
    };

    issue_kv(t0);

    float o[8][4];
    #pragma unroll
    for (int f = 0; f < 8; f++)
        #pragma unroll
        for (int e = 0; e < 4; e++) o[f][e] = 0.0f;
    float m_s[2] = {-1e30f, -1e30f};
    float l_s[2] = {0.0f, 0.0f};

    const int row0 = q0 + wr + (lane >> 2);
    const int row1 = row0 + 8;
    const uint32_t lrow = (lane & 15);
    const uint32_t koff = (lane >> 4) * 16;

    for (int t = t0; t < t1; ++t) {
        const int k0 = t * 64;
        CP_WAIT0();
        __syncthreads();
        if (t + 1 < t1) issue_kv(t + 1);

        const uint32_t kvb = sb + AKV + (uint32_t)(t & 1) * KVSTG;

        float sacc[8][4];
        #pragma unroll
        for (int f = 0; f < 8; f++)
            #pragma unroll
            for (int e = 0; e < 4; e++) sacc[f][e] = 0.0f;

        #pragma unroll
        for (int ks = 0; ks < 4; ks++) {
            uint32_t qh[4], ql[4];
            const uint32_t qoff = (uint32_t)(wr + lrow) * AROWB + ks * 32 + koff;
            ldsm_x4(qh, sb + AQH + qoff);
            ldsm_x4(ql, sb + AQL + qoff);
            const uint32_t cidx = ks * 2 + (lane >> 4);
            #pragma unroll
            for (int g = 0; g < 4; g++) {
                const uint32_t row = g * 16 + lrow;
                const uint32_t ro = row * 128 + ((cidx ^ (row & 7)) << 4);
                uint32_t kh[4], kl[4];
                ldsm_x4(kh, kvb + KH_O + ro);
                ldsm_x4(kl, kvb + KL_O + ro);
                mma_bf16(sacc[g * 2 + 0], qh, kh[0], kh[2]);
                mma_bf16(sacc[g * 2 + 0], qh, kl[0], kl[2]);
                mma_bf16(sacc[g * 2 + 0], ql, kh[0], kh[2]);
                mma_bf16(sacc[g * 2 + 1], qh, kh[1], kh[3]);
                mma_bf16(sacc[g * 2 + 1], qh, kl[1], kl[3]);
                mma_bf16(sacc[g * 2 + 1], ql, kh[1], kh[3]);
            }
        }

        const float scale = 0.125f;
        if (t >= 2 * qb) {
            #pragma unroll
            for (int f = 0; f < 8; f++) {
                const int cb = k0 + f * 8 + (lane & 3) * 2;
                sacc[f][0] = (cb     > row0) ? -1e30f : sacc[f][0] * scale;
                sacc[f][1] = (cb + 1 > row0) ? -1e30f : sacc[f][1] * scale;
                sacc[f][2] = (cb     > row1) ? -1e30f : sacc[f][2] * scale;
                sacc[f][3] = (cb + 1 > row1) ? -1e30f : sacc[f][3] * scale;
            }
        } else {
            #pragma unroll
            for (int f = 0; f < 8; f++)
                #pragma unroll
                for (int e = 0; e < 4; e++) sacc[f][e] *= scale;
        }

        float rm0 = -1e30f, rm1 = -1e30f;
        #pragma unroll
        for (int f = 0; f < 8; f++) {
            rm0 = fmaxf(rm0, fmaxf(sacc[f][0], sacc[f][1]));
            rm1 = fmaxf(rm1, fmaxf(sacc[f][2], sacc[f][3]));
        }
        #pragma unroll
        for (int off = 1; off < 4; off <<= 1) {
            rm0 = fmaxf(rm0, __shfl_xor_sync(0xffffffffu, rm0, off));
            rm1 = fmaxf(rm1, __shfl_xor_sync(0xffffffffu, rm1, off));
        }
        const float mn0 = fmaxf(m_s[0], rm0);
        const float mn1 = fmaxf(m_s[1], rm1);
        const float al0 = __expf(m_s[0] - mn0);
        const float al1 = __expf(m_s[1] - mn1);
        float rs0 = 0.0f, rs1 = 0.0f;
        #pragma unroll
        for (int f = 0; f < 8; f++) {
            sacc[f][0] = round_h(__expf(sacc[f][0] - mn0));
            sacc[f][1] = round_h(__expf(sacc[f][1] - mn0));
            sacc[f][2] = round_h(__expf(sacc[f][2] - mn1));
            sacc[f][3] = round_h(__expf(sacc[f][3] - mn1));
            rs0 += sacc[f][0] + sacc[f][1];
            rs1 += sacc[f][2] + sacc[f][3];
        }
        #pragma unroll
        for (int off = 1; off < 4; off <<= 1) {
            rs0 += __shfl_xor_sync(0xffffffffu, rs0, off);
            rs1 += __shfl_xor_sync(0xffffffffu, rs1, off);
        }
        l_s[0] = l_s[0] * al0 + rs0;
        l_s[1] = l_s[1] * al1 + rs1;
        m_s[0] = mn0;
        m_s[1] = mn1;
        #pragma unroll
        for (int f = 0; f < 8; f++) {
            o[f][0] *= al0; o[f][1] *= al0;
            o[f][2] *= al1; o[f][3] *= al1;
        }

        #pragma unroll
        for (int ks = 0; ks < 4; ks++) {
            const float* s0 = sacc[2 * ks];
            const float* s1 = sacc[2 * ks + 1];
            uint32_t ph[4];
            ph[0] = pack_h2(s0[0], s0[1]);
            ph[1] = pack_h2(s0[2], s0[3]);
            ph[2] = pack_h2(s1[0], s1[1]);
            ph[3] = pack_h2(s1[2], s1[3]);
            const uint32_t cidx = ks * 2 + (lane >> 4);
            #pragma unroll
            for (int g = 0; g < 4; g++) {
                const uint32_t row = g * 16 + lrow;
                const uint32_t ro = row * 128 + ((cidx ^ (row & 7)) << 4);
                uint32_t vv[4];
                ldsm_x4(vv, kvb + V_O + ro);
                mma_fp16(o[g * 2 + 0], ph, vv[0], vv[2]);
                mma_fp16(o[g * 2 + 1], ph, vv[1], vv[3]);
            }
        }
    }

    if (part == 255) {
        const float inv0 = 1.0f / l_s[0];
        const float inv1 = 1.0f / l_s[1];
        #pragma unroll
        for (int f = 0; f < 8; f++) {
            const int col = h * 64 + f * 8 + (lane & 3) * 2;
            uint32_t h0, l0, h1, l1;
            split2(o[f][0] * inv0, o[f][1] * inv0, h0, l0);
            split2(o[f][2] * inv1, o[f][3] * inv1, h1, l1);
            *(uint32_t*)&g_ctxh[(size_t)row0 * DM + col] = h0;
            *(uint32_t*)&g_ctxl[(size_t)row0 * DM + col] = l0;
            *(uint32_t*)&g_ctxh[(size_t)row1 * DM + col] = h1;
            *(uint32_t*)&g_ctxl[(size_t)row1 * DM + col] = l1;
        }
    } else {
        const int base = (h * 20 + (qb - 12)) * 128;
        const int r0 = base + (row0 - q0);
        const int r1 = base + (row1 - q0);
        g_pm[part][r0] = m_s[0];
        g_pl[part][r0] = l_s[0];
        g_pm[part][r1] = m_s[1];
        g_pl[part][r1] = l_s[1];
        #pragma unroll
        for (int f = 0; f < 8; f++) {
            const int d = f * 8 + (lane & 3) * 2;
            *(float2*)&g_pO[part][(size_t)r0 * DK + d] = make_float2(o[f][0], o[f][1]);
            *(float2*)&g_pO[part][(size_t)r1 * DK + d] = make_float2(o[f][2], o[f][3]);
        }
    }
}

// ---- merge split-K partials into ctx (exact; 2 or 3 parts by qb) ----
__global__ __launch_bounds__(256)
void attn_merge()
{
    const int tid = blockIdx.x * 256 + threadIdx.x;
    if (tid >= NSPLIT_ROWS * 32) return;
    const int rid = tid >> 5;
    const int d   = (tid & 31) * 2;

    const int h    = rid / (20 * 128);
    const int qbo  = (rid >> 7) % 20;
    const int qb   = 12 + qbo;
    const int nparts = (qb >= 24) ? 3 : 2;

    float M = fmaxf(g_pm[0][rid], g_pm[1][rid]);
    if (nparts == 3) M = fmaxf(M, g_pm[2][rid]);

    float lsum = 0.0f, va = 0.0f, vb = 0.0f;
    #pragma unroll
    for (int p = 0; p < 3; p++) {
        if (p >= nparts) break;
        const float w = __expf(g_pm[p][rid] - M);
        lsum += w * g_pl[p][rid];
        const float2 a = *(const float2*)&g_pO[p][(size_t)rid * DK + d];
        va += w * a.x;
        vb += w * a.y;
    }
    const float inv = 1.0f / lsum;
    va *= inv; vb *= inv;

    const int r    = rid & 127;
    const int grow = qb * 128 + r;
    const int col  = h * 64 + d;

    uint32_t hi, lo;
    split2(va, vb, hi, lo);
    *(uint32_t*)&g_ctxh[(size_t)grow * DM + col] = hi;
    *(uint32_t*)&g_ctxl[(size_t)grow * DM + col] = lo;
}

// ---------------------------------------------------------------------------
extern "C" void kernel_launch(void* const* d_in, const int* in_sizes, int n_in,
                              void* d_out, int out_size)
{
    const float* x  = (const float*)d_in[0];
    const float* Wq = (const float*)d_in[1];
    const float* Wk = (const float*)d_in[2];
    const float* Wv = (const float*)d_in[3];
    const float* Wo = (const float*)d_in[4];
    float* out = (float*)d_out;

    cudaFuncSetAttribute(gemm_qkv,
                         cudaFuncAttributeMaxDynamicSharedMemorySize, GEMM_SMEM_128);
    cudaFuncSetAttribute(gemm_out,
                         cudaFuncAttributeMaxDynamicSharedMemorySize, GEMM_SMEM_96);
    cudaFuncSetAttribute(attn_tc,
                         cudaFuncAttributeMaxDynamicSharedMemorySize, ATTN_SMEM);

    const int ntot4 = NX4 + 4 * NW4;
    split_all<<<(ntot4 + 255) / 256, 256>>>(x, Wq, Wk, Wv, Wo);

    gemm_qkv<<<dim3(S_LEN / 128, DM / 128, 3), 256, GEMM_SMEM_128>>>();

    attn_tc<<<dim3(ATTN_JOBS), 256, ATTN_SMEM>>>();
    attn_merge<<<(NSPLIT_ROWS * 32 + 255) / 256, 256>>>();

    gemm_out<<<dim3(S_LEN / 128, DM / 96), 256, GEMM_SMEM_96>>>(out);
}

// round 16
// speedup vs baseline: 1.2681x; 1.0878x over previous
#include <cuda_runtime.h>
#include <cuda_bf16.h>
#include <cuda_fp16.h>
#include <cstdint>

#define S_LEN 4096
#define DM    768
#define NH    12
#define DK    64

// ---------------- scratch (device globals) ----------------
__device__ __nv_bfloat16 g_xh[S_LEN * DM],  g_xl[S_LEN * DM];
__device__ __nv_bfloat16 g_Wqh[DM * DM],    g_Wql[DM * DM];
__device__ __nv_bfloat16 g_Wkh[DM * DM],    g_Wkl[DM * DM];
__device__ __nv_bfloat16 g_Wvh[DM * DM],    g_Wvl[DM * DM];
__device__ __nv_bfloat16 g_Woh[DM * DM],    g_Wol[DM * DM];
__device__ __half        g_Qt[S_LEN * DM];                      // Q fp16 single [s][hd]
__device__ __half        g_K16h[S_LEN * DM], g_K16l[S_LEN * DM]; // K fp16 hi/lo [s][hd]
__device__ __half        g_Vt[DM * S_LEN];                      // [hd][s], fp16
__device__ __nv_bfloat16 g_ctxh[S_LEN * DM], g_ctxl[S_LEN * DM];

// split-K partials: rows indexed (h, qb-12 in 0..19, r in 0..127)
#define NSPLIT_ROWS (NH * 20 * 128)      // 30720
__device__ float g_pm[3][NSPLIT_ROWS];
__device__ float g_pl[3][NSPLIT_ROWS];
__device__ float g_pO[3][NSPLIT_ROWS * DK];

// ---- LPT job table (unchanged from R15)
#define NJOBT 60
__constant__ uint8_t c_qb[NJOBT] = {
    23,23,11, 22,22, 21,21,31,31,10, 20,20,30,30,
    19,19,29,29,29,31,30,28,28, 9, 18,18,27,27,
    17,17,26,26,26,28,27,25,25, 8, 16,16,24,24,
    15,15,25,24, 7, 14,14, 13,13, 6, 12,12,
     5, 4, 3, 2, 1, 0 };
__constant__ uint8_t c_t0[NJOBT] = {
     0,24, 0,  0,23,  0,22, 0,22, 0,  0,21, 0,21,
     0,20, 0,20,40,44,42, 0,20, 0,  0,19, 0,19,
     0,18, 0,18,36,40,38, 0,18, 0,  0,17, 0,17,
     0,16,36,34, 0,  0,15,  0,14, 0,  0,13,
     0, 0, 0, 0, 0, 0 };
__constant__ uint8_t c_t1[NJOBT] = {
    24,48,24, 23,46, 22,44,22,44,22, 21,42,21,42,
    20,40,20,40,60,64,62,20,40,20, 19,38,19,38,
    18,36,18,36,54,58,56,18,36,18, 17,34,17,34,
    16,32,52,50,16, 15,30, 14,28,14, 13,26,
    12,10, 8, 6, 4, 2 };
__constant__ uint8_t c_pt[NJOBT] = {
     0,1,255, 0,1, 0,1,0,1,255, 0,1,0,1,
     0,1,0,1,2,2,2,0,1,255, 0,1,0,1,
     0,1,0,1,2,2,2,0,1,255, 0,1,0,1,
     0,1,2,2,255, 0,1, 0,1,255, 0,1,
     255,255,255,255,255,255 };
#define ATTN_JOBS (NJOBT * NH)           // 720

// ---------------- helpers ----------------
__device__ __forceinline__ uint32_t smem_u32(const void* p) {
    uint32_t a;
    asm("{ .reg .u64 t; cvta.to.shared.u64 t, %1; cvt.u32.u64 %0, t; }"
        : "=r"(a) : "l"(p));
    return a;
}
__device__ __forceinline__ void ldsm_x4(uint32_t* r, uint32_t addr) {
    asm volatile("ldmatrix.sync.aligned.m8n8.x4.shared.b16 {%0,%1,%2,%3}, [%4];"
                 : "=r"(r[0]), "=r"(r[1]), "=r"(r[2]), "=r"(r[3]) : "r"(addr));
}
__device__ __forceinline__ void mma_bf16(float* d, const uint32_t* a,
                                         uint32_t b0, uint32_t b1) {
    asm volatile("mma.sync.aligned.m16n8k16.row.col.f32.bf16.bf16.f32 "
                 "{%0,%1,%2,%3}, {%4,%5,%6,%7}, {%8,%9}, {%0,%1,%2,%3};"
                 : "+f"(d[0]), "+f"(d[1]), "+f"(d[2]), "+f"(d[3])
                 : "r"(a[0]), "r"(a[1]), "r"(a[2]), "r"(a[3]), "r"(b0), "r"(b1));
}
__device__ __forceinline__ void mma_fp16(float* d, const uint32_t* a,
                                         uint32_t b0, uint32_t b1) {
    asm volatile("mma.sync.aligned.m16n8k16.row.col.f32.f16.f16.f32 "
                 "{%0,%1,%2,%3}, {%4,%5,%6,%7}, {%8,%9}, {%0,%1,%2,%3};"
                 : "+f"(d[0]), "+f"(d[1]), "+f"(d[2]), "+f"(d[3])
                 : "r"(a[0]), "r"(a[1]), "r"(a[2]), "r"(a[3]), "r"(b0), "r"(b1));
}
__device__ __forceinline__ void sts_v4(uint32_t addr, uint4 v) {
    asm volatile("st.shared.v4.b32 [%0], {%1, %2, %3, %4};"
                 :: "r"(addr), "r"(v.x), "r"(v.y), "r"(v.z), "r"(v.w) : "memory");
}
__device__ __forceinline__ void split2(float x, float y, uint32_t& hi, uint32_t& lo) {
    __nv_bfloat16 hx = __float2bfloat16(x), hy = __float2bfloat16(y);
    __nv_bfloat162 h2 = {hx, hy};
    hi = *(uint32_t*)&h2;
    __nv_bfloat162 l2 = {__float2bfloat16(x - __bfloat162float(hx)),
                         __float2bfloat16(y - __bfloat162float(hy))};
    lo = *(uint32_t*)&l2;
}
// fp16 hi/lo split
__device__ __forceinline__ void split2h(float x, float y, uint32_t& hi, uint32_t& lo) {
    __half hx = __float2half_rn(x), hy = __float2half_rn(y);
    __half2 h2 = {hx, hy};
    hi = *(uint32_t*)&h2;
    __half2 l2 = {__float2half_rn(x - __half2float(hx)),
                  __float2half_rn(y - __half2float(hy))};
    lo = *(uint32_t*)&l2;
}
__device__ __forceinline__ uint32_t pack_h2(float x, float y) {
    __half2 h = __floats2half2_rn(x, y);
    return *(uint32_t*)&h;
}
__device__ __forceinline__ float round_h(float x) {
    return __half2float(__float2half_rn(x));
}
__device__ __forceinline__ void cp_async16(uint32_t dst, const void* src) {
    asm volatile("cp.async.cg.shared.global [%0], [%1], 16;"
                 :: "r"(dst), "l"(src));
}
#define CP_COMMIT() asm volatile("cp.async.commit_group;" ::: "memory")
#define CP_WAIT0()  asm volatile("cp.async.wait_group 0;" ::: "memory")

// ---------------- single fp32 -> bf16 hi/lo split pass ----------------
#define NX4 (S_LEN * DM / 4)
#define NW4 (DM * DM / 4)

__global__ __launch_bounds__(256)
void split_all(const float* __restrict__ x,  const float* __restrict__ Wq,
               const float* __restrict__ Wk, const float* __restrict__ Wv,
               const float* __restrict__ Wo)
{
    int i = blockIdx.x * blockDim.x + threadIdx.x;
    const float* in;
    __nv_bfloat16 *hi, *lo;
    int j = i;
    if (j < NX4)            { in = x;  hi = g_xh;  lo = g_xl;  }
    else if ((j -= NX4) < NW4)   { in = Wq; hi = g_Wqh; lo = g_Wql; }
    else if ((j -= NW4) < NW4)   { in = Wk; hi = g_Wkh; lo = g_Wkl; }
    else if ((j -= NW4) < NW4)   { in = Wv; hi = g_Wvh; lo = g_Wvl; }
    else if ((j -= NW4) < NW4)   { in = Wo; hi = g_Woh; lo = g_Wol; }
    else return;
    float4 v = ((const float4*)in)[j];
    uint32_t h0, l0, h1, l1;
    split2(v.x, v.y, h0, l0);
    split2(v.z, v.w, h1, l1);
    ((uint2*)hi)[j] = make_uint2(h0, h1);
    ((uint2*)lo)[j] = make_uint2(l0, l1);
}

// ===========================================================================
// bf16x3 GEMM body.  OMODE: 0 fp32 C, 1 bf16 hi/lo, 2 fp16 single,
//                           3 fp16 hi/lo (Cf16, Cf16l).
// ===========================================================================
#define ROWB      80
#define TILE_A    (128 * ROWB)

template<int OMODE, int BNR>
__device__ __forceinline__
void gemm_body(const __nv_bfloat16* __restrict__ Ah, const __nv_bfloat16* __restrict__ Al,
               const __nv_bfloat16* __restrict__ Bh, const __nv_bfloat16* __restrict__ Bl,
               float* __restrict__ C,
               __nv_bfloat16* __restrict__ Ch, __nv_bfloat16* __restrict__ Cl,
               __half* __restrict__ Cf16, __half* __restrict__ Cf16l,
               int M, int N, int K, int bm, int bn, uint32_t sbase)
{
    constexpr int TILE_BB = BNR * ROWB;
    constexpr int BUF_B   = 2 * TILE_A + 2 * TILE_BB;
    constexpr int AHI = 0, ALO = TILE_A, BHI = 2 * TILE_A, BLO = 2 * TILE_A + TILE_BB;
    constexpr int NF = BNR / 16;
    constexpr int NCP = (1024 + BNR * 8) / 256;

    const int tid  = threadIdx.x;
    const int lane = tid & 31;
    const int warp = tid >> 5;
    const int m0 = (warp >> 1) * 32;
    const int n0 = (warp & 1) * (BNR / 2);

    float acc[2][NF][4];
    #pragma unroll
    for (int mt = 0; mt < 2; mt++)
        #pragma unroll
        for (int nf = 0; nf < NF; nf++)
            #pragma unroll
            for (int e = 0; e < 4; e++) acc[mt][nf][e] = 0.0f;

    const int nchunk = K / 32;

    auto issue = [&](int c) {
        const uint32_t buf = sbase + (uint32_t)(c & 1) * BUF_B;
        const int kc = c * 32;
        #pragma unroll
        for (int j = 0; j < NCP; j++) {
            const int idx = tid + j * 256;
            uint32_t dst;
            const __nv_bfloat16* src;
            if (idx < 512) {
                const int row = idx >> 2, ch = idx & 3;
                dst = buf + AHI + row * ROWB + ch * 16;
                src = &Ah[(size_t)(bm + row) * K + kc + ch * 8];
            } else if (idx < 1024) {
                const int r2 = idx - 512;
                const int row = r2 >> 2, ch = r2 & 3;
                dst = buf + ALO + row * ROWB + ch * 16;
                src = &Al[(size_t)(bm + row) * K + kc + ch * 8];
            } else if (idx < 1024 + BNR * 4) {
                const int r2 = idx - 1024;
                const int row = r2 >> 2, ch = r2 & 3;
                dst = buf + BHI + row * ROWB + ch * 16;
                src = &Bh[(size_t)(bn + row) * K + kc + ch * 8];
            } else {
                const int r2 = idx - (1024 + BNR * 4);
                const int row = r2 >> 2, ch = r2 & 3;
                dst = buf + BLO + row * ROWB + ch * 16;
                src = &Bl[(size_t)(bn + row) * K + kc + ch * 8];
            }
            cp_async16(dst, src);
        }
        CP_COMMIT();
    };

    issue(0);

    const uint32_t lrow = (lane & 15);
    const uint32_t koff = (lane >> 4) * 16;

    for (int c = 0; c < nchunk; ++c) {
        CP_WAIT0();
        __syncthreads();
        if (c + 1 < nchunk) issue(c + 1);

        const uint32_t buf = sbase + (uint32_t)(c & 1) * BUF_B;
        #pragma unroll
        for (int ks = 0; ks < 2; ks++) {
            const uint32_t kb = ks * 32 + koff;
            uint32_t ah[2][4], al[2][4];
            #pragma unroll
            for (int mt = 0; mt < 2; mt++) {
                const uint32_t ro = (uint32_t)(m0 + mt * 16 + lrow) * ROWB + kb;
                ldsm_x4(ah[mt], buf + AHI + ro);
                ldsm_x4(al[mt], buf + ALO + ro);
            }
            uint32_t bh[NF / 2][4], bl[NF / 2][4];
            #pragma unroll
            for (int g = 0; g < NF / 2; g++) {
                const uint32_t ro = (uint32_t)(n0 + g * 16 + lrow) * ROWB + kb;
                ldsm_x4(bh[g], buf + BHI + ro);
                ldsm_x4(bl[g], buf + BLO + ro);
            }
            #pragma unroll
            for (int mt = 0; mt < 2; mt++) {
                #pragma unroll
                for (int g = 0; g < NF / 2; g++) {
                    mma_bf16(acc[mt][g * 2 + 0], ah[mt], bh[g][0], bh[g][2]);
                    mma_bf16(acc[mt][g * 2 + 0], ah[mt], bl[g][0], bl[g][2]);
                    mma_bf16(acc[mt][g * 2 + 0], al[mt], bh[g][0], bh[g][2]);
                    mma_bf16(acc[mt][g * 2 + 1], ah[mt], bh[g][1], bh[g][3]);
                    mma_bf16(acc[mt][g * 2 + 1], ah[mt], bl[g][1], bl[g][3]);
                    mma_bf16(acc[mt][g * 2 + 1], al[mt], bh[g][1], bh[g][3]);
                }
            }
        }
        __syncthreads();
    }

    #pragma unroll
    for (int mt = 0; mt < 2; mt++) {
        const int row = bm + m0 + mt * 16 + (lane >> 2);
        #pragma unroll
        for (int nf = 0; nf < NF; nf++) {
            const int col = bn + n0 + nf * 8 + (lane & 3) * 2;
            if (OMODE == 0) {
                *(float2*)&C[(size_t)row * N + col] =
                    make_float2(acc[mt][nf][0], acc[mt][nf][1]);
                *(float2*)&C[(size_t)(row + 8) * N + col] =
                    make_float2(acc[mt][nf][2], acc[mt][nf][3]);
            } else if (OMODE == 1) {
                uint32_t h0, l0, h1, l1;
                split2(acc[mt][nf][0], acc[mt][nf][1], h0, l0);
                split2(acc[mt][nf][2], acc[mt][nf][3], h1, l1);
                *(uint32_t*)&Ch[(size_t)row * N + col]       = h0;
                *(uint32_t*)&Cl[(size_t)row * N + col]       = l0;
                *(uint32_t*)&Ch[(size_t)(row + 8) * N + col] = h1;
                *(uint32_t*)&Cl[(size_t)(row + 8) * N + col] = l1;
            } else if (OMODE == 2) {
                *(uint32_t*)&Cf16[(size_t)row * N + col] =
                    pack_h2(acc[mt][nf][0], acc[mt][nf][1]);
                *(uint32_t*)&Cf16[(size_t)(row + 8) * N + col] =
                    pack_h2(acc[mt][nf][2], acc[mt][nf][3]);
            } else {
                uint32_t h0, l0, h1, l1;
                split2h(acc[mt][nf][0], acc[mt][nf][1], h0, l0);
                split2h(acc[mt][nf][2], acc[mt][nf][3], h1, l1);
                *(uint32_t*)&Cf16[(size_t)row * N + col]        = h0;
                *(uint32_t*)&Cf16l[(size_t)row * N + col]       = l0;
                *(uint32_t*)&Cf16[(size_t)(row + 8) * N + col]  = h1;
                *(uint32_t*)&Cf16l[(size_t)(row + 8) * N + col] = l1;
            }
        }
    }
}

#define GEMM_SMEM_128 (2 * (2 * TILE_A + 2 * 128 * ROWB))   // 81920
#define GEMM_SMEM_96  (2 * (2 * TILE_A + 2 * 96 * ROWB))    // 71680

__global__ __launch_bounds__(256, 2)
void gemm_qkv()
{
    extern __shared__ __align__(128) char dynsm[];
    const uint32_t sbase = smem_u32(dynsm);
    const int z = blockIdx.z;

    if (z == 0) {
        // Q: single fp16
        gemm_body<2, 128>(g_xh, g_xl, g_Wqh, g_Wql, nullptr, nullptr, nullptr,
                          g_Qt, nullptr,
                          S_LEN, DM, DM, blockIdx.x * 128, blockIdx.y * 128, sbase);
    } else if (z == 1) {
        // K: fp16 hi/lo
        gemm_body<3, 128>(g_xh, g_xl, g_Wkh, g_Wkl, nullptr, nullptr, nullptr,
                          g_K16h, g_K16l,
                          S_LEN, DM, DM, blockIdx.x * 128, blockIdx.y * 128, sbase);
    } else {
        gemm_body<2, 128>(g_Wvh, g_Wvl, g_xh, g_xl, nullptr, nullptr, nullptr,
                          g_Vt, nullptr,
                          DM, S_LEN, DM, blockIdx.y * 128, blockIdx.x * 128, sbase);
    }
}

// Output projection: 128x96 tiles -> 256 CTAs = single wave at 2 CTA/SM
__global__ __launch_bounds__(256, 2)
void gemm_out(float* __restrict__ out)
{
    extern __shared__ __align__(128) char dynsm[];
    const uint32_t sbase = smem_u32(dynsm);
    gemm_body<0, 96>(g_ctxh, g_ctxl, g_Woh, g_Wol, out, nullptr, nullptr,
                     nullptr, nullptr,
                     S_LEN, DM, DM, blockIdx.x * 128, blockIdx.y * 96, sbase);
}

// ===========================================================================
// Attention: QK fp16x2 (Qh single fp16; K fp16 hi/lo) — 2 mma/fragment.
// PV single fp16 (P fp16-exact, l from rounded P). Split-K + LPT (R15).
// ===========================================================================
#define AROWB 144
#define AQ    0
#define AKV   (128 * AROWB)              // 18432 (Q fp16 single)
#define KVSTG 24576                      // Kh 8K + Kl 8K + V 8K (all fp16)
#define KH_O  0
#define KL_O  8192
#define V_O   16384
#define ATTN_SMEM (AKV + 2 * KVSTG)      // 67584

__global__ __launch_bounds__(256, 2)
void attn_tc()
{
    extern __shared__ __align__(128) char dynbuf[];
    const uint32_t sb = smem_u32(dynbuf);

    const int tid  = threadIdx.x;
    const int lane = tid & 31;
    const int warp = tid >> 5;
    const int wr   = warp * 16;

    const int type = blockIdx.x / NH;
    const int h    = blockIdx.x % NH;
    const int qb   = c_qb[type];
    const int t0   = c_t0[type];
    const int t1   = c_t1[type];
    const int part = c_pt[type];
    const int q0   = qb * 128;

    // ---- load Q tile (fp16 single) ----
    {
        const int gr = tid >> 3;
        const int gc = tid & 7;
        #pragma unroll
        for (int i = 0; i < 2; i++) {
            const int r = gr * 2 + (i & 1) + (i >> 1) * 64;   // rows 0..63 pairs
            // simpler: 1024 16B-chunks over 128 rows x 8 chunks -> 2 iters of 512
            const int idx = tid + i * 256;                    // 0..511
            const int row = idx >> 2;                         // 0..127
            const int ch  = idx & 3;                          // 4 chunks of 16B? no:
            (void)r; (void)gc; (void)gr;
            // row has 128B = 8 chunks of 16B; use idx2 mapping below instead
            (void)row; (void)ch;
        }
        // clean mapping: 128 rows x 8 x 16B = 1024 chunks, 256 threads x 4
        #pragma unroll
        for (int i = 0; i < 4; i++) {
            const int idx = tid + i * 256;       // 0..1023
            const int row = idx >> 3;            // 0..127
            const int ch  = idx & 7;             // 0..7
            const uint32_t soff = (uint32_t)row * AROWB + ch * 16;
            uint4 v = *(const uint4*)&g_Qt[(size_t)(q0 + row) * DM + h * 64 + ch * 8];
            sts_v4(sb + AQ + soff, v);
        }
    }

    auto issue_kv = [&](int t) {
        const uint32_t kvb = sb + AKV + (uint32_t)(t & 1) * KVSTG;
        const int k0 = t * 64;
        #pragma unroll
        for (int j = 0; j < 6; j++) {
            const int idx = tid + j * 256;
            const int arr = idx >> 9;
            const int rem2 = idx & 511;
            const int row = rem2 >> 3;
            const int c   = rem2 & 7;
            const uint32_t dst = kvb + (uint32_t)arr * 8192 + row * 128 +
                                 ((uint32_t)(c ^ (row & 7)) << 4);
            const void* src;
            if (arr == 0)      src = &g_K16h[(size_t)(k0 + row) * DM + h * 64 + c * 8];
            else if (arr == 1) src = &g_K16l[(size_t)(k0 + row) * DM + h * 64 + c * 8];
            else               src = &g_Vt[(size_t)(h * 64 + row) * S_LEN + k0 + c * 8];
            cp_async16(dst, src);
        }
        CP_COMMIT();
    };

    issue_kv(t0);

    float o[8][4];
    #pragma unroll
    for (int f = 0; f < 8; f++)
        #pragma unroll
        for (int e = 0; e < 4; e++) o[f][e] = 0.0f;
    float m_s[2] = {-1e30f, -1e30f};
    float l_s[2] = {0.0f, 0.0f};

    const int row0 = q0 + wr + (lane >> 2);
    const int row1 = row0 + 8;
    const uint32_t lrow = (lane & 15);
    const uint32_t koff = (lane >> 4) * 16;

    for (int t = t0; t < t1; ++t) {
        const int k0 = t * 64;
        CP_WAIT0();
        __syncthreads();
        if (t + 1 < t1) issue_kv(t + 1);

        const uint32_t kvb = sb + AKV + (uint32_t)(t & 1) * KVSTG;

        float sacc[8][4];
        #pragma unroll
        for (int f = 0; f < 8; f++)
            #pragma unroll
            for (int e = 0; e < 4; e++) sacc[f][e] = 0.0f;

        // ---- S = Q K^T (fp16x2: Qh·Kh + Qh·Kl) ----
        #pragma unroll
        for (int ks = 0; ks < 4; ks++) {
            uint32_t qh[4];
            const uint32_t qoff = (uint32_t)(wr + lrow) * AROWB + ks * 32 + koff;
            ldsm_x4(qh, sb + AQ + qoff);
            const uint32_t cidx = ks * 2 + (lane >> 4);
            #pragma unroll
            for (int g = 0; g < 4; g++) {
                const uint32_t row = g * 16 + lrow;
                const uint32_t ro = row * 128 + ((cidx ^ (row & 7)) << 4);
                uint32_t kh[4], kl[4];
                ldsm_x4(kh, kvb + KH_O + ro);
                ldsm_x4(kl, kvb + KL_O + ro);
                mma_fp16(sacc[g * 2 + 0], qh, kh[0], kh[2]);
                mma_fp16(sacc[g * 2 + 0], qh, kl[0], kl[2]);
                mma_fp16(sacc[g * 2 + 1], qh, kh[1], kh[3]);
                mma_fp16(sacc[g * 2 + 1], qh, kl[1], kl[3]);
            }
        }

        const float scale = 0.125f;
        if (t >= 2 * qb) {
            #pragma unroll
            for (int f = 0; f < 8; f++) {
                const int cb = k0 + f * 8 + (lane & 3) * 2;
                sacc[f][0] = (cb     > row0) ? -1e30f : sacc[f][0] * scale;
                sacc[f][1] = (cb + 1 > row0) ? -1e30f : sacc[f][1] * scale;
                sacc[f][2] = (cb     > row1) ? -1e30f : sacc[f][2] * scale;
                sacc[f][3] = (cb + 1 > row1) ? -1e30f : sacc[f][3] * scale;
            }
        } else {
            #pragma unroll
            for (int f = 0; f < 8; f++)
                #pragma unroll
                for (int e = 0; e < 4; e++) sacc[f][e] *= scale;
        }

        float rm0 = -1e30f, rm1 = -1e30f;
        #pragma unroll
        for (int f = 0; f < 8; f++) {
            rm0 = fmaxf(rm0, fmaxf(sacc[f][0], sacc[f][1]));
            rm1 = fmaxf(rm1, fmaxf(sacc[f][2], sacc[f][3]));
        }
        #pragma unroll
        for (int off = 1; off < 4; off <<= 1) {
            rm0 = fmaxf(rm0, __shfl_xor_sync(0xffffffffu, rm0, off));
            rm1 = fmaxf(rm1, __shfl_xor_sync(0xffffffffu, rm1, off));
        }
        const float mn0 = fmaxf(m_s[0], rm0);
        const float mn1 = fmaxf(m_s[1], rm1);
        const float al0 = __expf(m_s[0] - mn0);
        const float al1 = __expf(m_s[1] - mn1);
        float rs0 = 0.0f, rs1 = 0.0f;
        #pragma unroll
        for (int f = 0; f < 8; f++) {
            sacc[f][0] = round_h(__expf(sacc[f][0] - mn0));
            sacc[f][1] = round_h(__expf(sacc[f][1] - mn0));
            sacc[f][2] = round_h(__expf(sacc[f][2] - mn1));
            sacc[f][3] = round_h(__expf(sacc[f][3] - mn1));
            rs0 += sacc[f][0] + sacc[f][1];
            rs1 += sacc[f][2] + sacc[f][3];
        }
        #pragma unroll
        for (int off = 1; off < 4; off <<= 1) {
            rs0 += __shfl_xor_sync(0xffffffffu, rs0, off);
            rs1 += __shfl_xor_sync(0xffffffffu, rs1, off);
        }
        l_s[0] = l_s[0] * al0 + rs0;
        l_s[1] = l_s[1] * al1 + rs1;
        m_s[0] = mn0;
        m_s[1] = mn1;
        #pragma unroll
        for (int f = 0; f < 8; f++) {
            o[f][0] *= al0; o[f][1] *= al0;
            o[f][2] *= al1; o[f][3] *= al1;
        }

        #pragma unroll
        for (int ks = 0; ks < 4; ks++) {
            const float* s0 = sacc[2 * ks];
            const float* s1 = sacc[2 * ks + 1];
            uint32_t ph[4];
            ph[0] = pack_h2(s0[0], s0[1]);
            ph[1] = pack_h2(s0[2], s0[3]);
            ph[2] = pack_h2(s1[0], s1[1]);
            ph[3] = pack_h2(s1[2], s1[3]);
            const uint32_t cidx = ks * 2 + (lane >> 4);
            #pragma unroll
            for (int g = 0; g < 4; g++) {
                const uint32_t row = g * 16 + lrow;
                const uint32_t ro = row * 128 + ((cidx ^ (row & 7)) << 4);
                uint32_t vv[4];
                ldsm_x4(vv, kvb + V_O + ro);
                mma_fp16(o[g * 2 + 0], ph, vv[0], vv[2]);
                mma_fp16(o[g * 2 + 1], ph, vv[1], vv[3]);
            }
        }
    }

    if (part == 255) {
        const float inv0 = 1.0f / l_s[0];
        const float inv1 = 1.0f / l_s[1];
        #pragma unroll
        for (int f = 0; f < 8; f++) {
            const int col = h * 64 + f * 8 + (lane & 3) * 2;
            uint32_t h0, l0, h1, l1;
            split2(o[f][0] * inv0, o[f][1] * inv0, h0, l0);
            split2(o[f][2] * inv1, o[f][3] * inv1, h1, l1);
            *(uint32_t*)&g_ctxh[(size_t)row0 * DM + col] = h0;
            *(uint32_t*)&g_ctxl[(size_t)row0 * DM + col] = l0;
            *(uint32_t*)&g_ctxh[(size_t)row1 * DM + col] = h1;
            *(uint32_t*)&g_ctxl[(size_t)row1 * DM + col] = l1;
        }
    } else {
        const int base = (h * 20 + (qb - 12)) * 128;
        const int r0 = base + (row0 - q0);
        const int r1 = base + (row1 - q0);
        g_pm[part][r0] = m_s[0];
        g_pl[part][r0] = l_s[0];
        g_pm[part][r1] = m_s[1];
        g_pl[part][r1] = l_s[1];
        #pragma unroll
        for (int f = 0; f < 8; f++) {
            const int d = f * 8 + (lane & 3) * 2;
            *(float2*)&g_pO[part][(size_t)r0 * DK + d] = make_float2(o[f][0], o[f][1]);
            *(float2*)&g_pO[part][(size_t)r1 * DK + d] = make_float2(o[f][2], o[f][3]);
        }
    }
}

// ---- merge split-K partials into ctx (exact; 2 or 3 parts by qb) ----
__global__ __launch_bounds__(256)
void attn_merge()
{
    const int tid = blockIdx.x * 256 + threadIdx.x;
    if (tid >= NSPLIT_ROWS * 32) return;
    const int rid = tid >> 5;
    const int d   = (tid & 31) * 2;

    const int h    = rid / (20 * 128);
    const int qbo  = (rid >> 7) % 20;
    const int qb   = 12 + qbo;
    const int nparts = (qb >= 24) ? 3 : 2;

    float M = fmaxf(g_pm[0][rid], g_pm[1][rid]);
    if (nparts == 3) M = fmaxf(M, g_pm[2][rid]);

    float lsum = 0.0f, va = 0.0f, vb = 0.0f;
    #pragma unroll
    for (int p = 0; p < 3; p++) {
        if (p >= nparts) break;
        const float w = __expf(g_pm[p][rid] - M);
        lsum += w * g_pl[p][rid];
        const float2 a = *(const float2*)&g_pO[p][(size_t)rid * DK + d];
        va += w * a.x;
        vb += w * a.y;
    }
    const float inv = 1.0f / lsum;
    va *= inv; vb *= inv;

    const int r    = rid & 127;
    const int grow = qb * 128 + r;
    const int col  = h * 64 + d;

    uint32_t hi, lo;
    split2(va, vb, hi, lo);
    *(uint32_t*)&g_ctxh[(size_t)grow * DM + col] = hi;
    *(uint32_t*)&g_ctxl[(size_t)grow * DM + col] = lo;
}

// ---------------------------------------------------------------------------
extern "C" void kernel_launch(void* const* d_in, const int* in_sizes, int n_in,
                              void* d_out, int out_size)
{
    const float* x  = (const float*)d_in[0];
    const float* Wq = (const float*)d_in[1];
    const float* Wk = (const float*)d_in[2];
    const float* Wv = (const float*)d_in[3];
    const float* Wo = (const float*)d_in[4];
    float* out = (float*)d_out;

    cudaFuncSetAttribute(gemm_qkv,
                         cudaFuncAttributeMaxDynamicSharedMemorySize, GEMM_SMEM_128);
    cudaFuncSetAttribute(gemm_out,
                         cudaFuncAttributeMaxDynamicSharedMemorySize, GEMM_SMEM_96);
    cudaFuncSetAttribute(attn_tc,
                         cudaFuncAttributeMaxDynamicSharedMemorySize, ATTN_SMEM);

    const int ntot4 = NX4 + 4 * NW4;
    split_all<<<(ntot4 + 255) / 256, 256>>>(x, Wq, Wk, Wv, Wo);

    gemm_qkv<<<dim3(S_LEN / 128, DM / 128, 3), 256, GEMM_SMEM_128>>>();

    attn_tc<<<dim3(ATTN_JOBS), 256, ATTN_SMEM>>>();
    attn_merge<<<(NSPLIT_ROWS * 32 + 255) / 256, 256>>>();

    gemm_out<<<dim3(S_LEN / 128, DM / 96), 256, GEMM_SMEM_96>>>(out);
}

// round 17
// speedup vs baseline: 1.4102x; 1.1121x over previous
#include <cuda_runtime.h>
#include <cuda_bf16.h>
#include <cuda_fp16.h>
#include <cstdint>

#define S_LEN 4096
#define DM    768
#define NH    12
#define DK    64

// ---------------- scratch (device globals) ----------------
__device__ __half        g_x16[S_LEN * DM];                      // x fp16 single
__device__ __half        g_x16h[S_LEN * DM], g_x16l[S_LEN * DM]; // x fp16 hi/lo
__device__ __half        g_Wq16h[DM * DM],   g_Wq16l[DM * DM];
__device__ __half        g_Wk16h[DM * DM],   g_Wk16l[DM * DM];
__device__ __half        g_Wv16[DM * DM];                        // Wv fp16 single
__device__ __nv_bfloat16 g_Woh[DM * DM],     g_Wol[DM * DM];
__device__ __half        g_Qt[S_LEN * DM];                       // Q fp16 [s][hd]
__device__ __half        g_K16h[S_LEN * DM], g_K16l[S_LEN * DM]; // K fp16 hi/lo
__device__ __half        g_Vt[DM * S_LEN];                       // V^T fp16 [hd][s]
__device__ __nv_bfloat16 g_ctxh[S_LEN * DM], g_ctxl[S_LEN * DM];

// split-K partials: rows indexed (h, qb-12 in 0..19, r in 0..127)
#define NSPLIT_ROWS (NH * 20 * 128)      // 30720
__device__ float g_pm[3][NSPLIT_ROWS];
__device__ float g_pl[3][NSPLIT_ROWS];
__device__ float g_pO[3][NSPLIT_ROWS * DK];

// ---- LPT job table (unchanged)
#define NJOBT 60
__constant__ uint8_t c_qb[NJOBT] = {
    23,23,11, 22,22, 21,21,31,31,10, 20,20,30,30,
    19,19,29,29,29,31,30,28,28, 9, 18,18,27,27,
    17,17,26,26,26,28,27,25,25, 8, 16,16,24,24,
    15,15,25,24, 7, 14,14, 13,13, 6, 12,12,
     5, 4, 3, 2, 1, 0 };
__constant__ uint8_t c_t0[NJOBT] = {
     0,24, 0,  0,23,  0,22, 0,22, 0,  0,21, 0,21,
     0,20, 0,20,40,44,42, 0,20, 0,  0,19, 0,19,
     0,18, 0,18,36,40,38, 0,18, 0,  0,17, 0,17,
     0,16,36,34, 0,  0,15,  0,14, 0,  0,13,
     0, 0, 0, 0, 0, 0 };
__constant__ uint8_t c_t1[NJOBT] = {
    24,48,24, 23,46, 22,44,22,44,22, 21,42,21,42,
    20,40,20,40,60,64,62,20,40,20, 19,38,19,38,
    18,36,18,36,54,58,56,18,36,18, 17,34,17,34,
    16,32,52,50,16, 15,30, 14,28,14, 13,26,
    12,10, 8, 6, 4, 2 };
__constant__ uint8_t c_pt[NJOBT] = {
     0,1,255, 0,1, 0,1,0,1,255, 0,1,0,1,
     0,1,0,1,2,2,2,0,1,255, 0,1,0,1,
     0,1,0,1,2,2,2,0,1,255, 0,1,0,1,
     0,1,2,2,255, 0,1, 0,1,255, 0,1,
     255,255,255,255,255,255 };
#define ATTN_JOBS (NJOBT * NH)           // 720

// ---------------- helpers ----------------
__device__ __forceinline__ uint32_t smem_u32(const void* p) {
    uint32_t a;
    asm("{ .reg .u64 t; cvta.to.shared.u64 t, %1; cvt.u32.u64 %0, t; }"
        : "=r"(a) : "l"(p));
    return a;
}
__device__ __forceinline__ void ldsm_x4(uint32_t* r, uint32_t addr) {
    asm volatile("ldmatrix.sync.aligned.m8n8.x4.shared.b16 {%0,%1,%2,%3}, [%4];"
                 : "=r"(r[0]), "=r"(r[1]), "=r"(r[2]), "=r"(r[3]) : "r"(addr));
}
__device__ __forceinline__ void mma_bf16(float* d, const uint32_t* a,
                                         uint32_t b0, uint32_t b1) {
    asm volatile("mma.sync.aligned.m16n8k16.row.col.f32.bf16.bf16.f32 "
                 "{%0,%1,%2,%3}, {%4,%5,%6,%7}, {%8,%9}, {%0,%1,%2,%3};"
                 : "+f"(d[0]), "+f"(d[1]), "+f"(d[2]), "+f"(d[3])
                 : "r"(a[0]), "r"(a[1]), "r"(a[2]), "r"(a[3]), "r"(b0), "r"(b1));
}
__device__ __forceinline__ void mma_fp16(float* d, const uint32_t* a,
                                         uint32_t b0, uint32_t b1) {
    asm volatile("mma.sync.aligned.m16n8k16.row.col.f32.f16.f16.f32 "
                 "{%0,%1,%2,%3}, {%4,%5,%6,%7}, {%8,%9}, {%0,%1,%2,%3};"
                 : "+f"(d[0]), "+f"(d[1]), "+f"(d[2]), "+f"(d[3])
                 : "r"(a[0]), "r"(a[1]), "r"(a[2]), "r"(a[3]), "r"(b0), "r"(b1));
}
__device__ __forceinline__ void sts_v4(uint32_t addr, uint4 v) {
    asm volatile("st.shared.v4.b32 [%0], {%1, %2, %3, %4};"
                 :: "r"(addr), "r"(v.x), "r"(v.y), "r"(v.z), "r"(v.w) : "memory");
}
__device__ __forceinline__ void split2(float x, float y, uint32_t& hi, uint32_t& lo) {
    __nv_bfloat16 hx = __float2bfloat16(x), hy = __float2bfloat16(y);
    __nv_bfloat162 h2 = {hx, hy};
    hi = *(uint32_t*)&h2;
    __nv_bfloat162 l2 = {__float2bfloat16(x - __bfloat162float(hx)),
                         __float2bfloat16(y - __bfloat162float(hy))};
    lo = *(uint32_t*)&l2;
}
__device__ __forceinline__ void split2h(float x, float y, uint32_t& hi, uint32_t& lo) {
    __half hx = __float2half_rn(x), hy = __float2half_rn(y);
    __half2 h2 = {hx, hy};
    hi = *(uint32_t*)&h2;
    __half2 l2 = {__float2half_rn(x - __half2float(hx)),
                  __float2half_rn(y - __half2float(hy))};
    lo = *(uint32_t*)&l2;
}
__device__ __forceinline__ uint32_t pack_h2(float x, float y) {
    __half2 h = __floats2half2_rn(x, y);
    return *(uint32_t*)&h;
}
__device__ __forceinline__ float round_h(float x) {
    return __half2float(__float2half_rn(x));
}
__device__ __forceinline__ void cp_async16(uint32_t dst, const void* src) {
    asm volatile("cp.async.cg.shared.global [%0], [%1], 16;"
                 :: "r"(dst), "l"(src));
}
#define CP_COMMIT() asm volatile("cp.async.commit_group;" ::: "memory")
#define CP_WAIT0()  asm volatile("cp.async.wait_group 0;" ::: "memory")

// ---------------- fp32 -> fp16/bf16 split pass ----------------
#define NX4 (S_LEN * DM / 4)
#define NW4 (DM * DM / 4)

__global__ __launch_bounds__(256)
void split_all(const float* __restrict__ x,  const float* __restrict__ Wq,
               const float* __restrict__ Wk, const float* __restrict__ Wv,
               const float* __restrict__ Wo)
{
    int i = blockIdx.x * blockDim.x + threadIdx.x;
    int j = i;
    if (j < NX4) {
        float4 v = ((const float4*)x)[j];
        uint32_t h0, l0, h1, l1;
        split2h(v.x, v.y, h0, l0);
        split2h(v.z, v.w, h1, l1);
        ((uint2*)g_x16)[j]  = make_uint2(h0, h1);   // single = hi
        ((uint2*)g_x16h)[j] = make_uint2(h0, h1);
        ((uint2*)g_x16l)[j] = make_uint2(l0, l1);
        return;
    }
    j -= NX4;
    if (j < NW4) {
        float4 v = ((const float4*)Wq)[j];
        uint32_t h0, l0, h1, l1;
        split2h(v.x, v.y, h0, l0);
        split2h(v.z, v.w, h1, l1);
        ((uint2*)g_Wq16h)[j] = make_uint2(h0, h1);
        ((uint2*)g_Wq16l)[j] = make_uint2(l0, l1);
        return;
    }
    j -= NW4;
    if (j < NW4) {
        float4 v = ((const float4*)Wk)[j];
        uint32_t h0, l0, h1, l1;
        split2h(v.x, v.y, h0, l0);
        split2h(v.z, v.w, h1, l1);
        ((uint2*)g_Wk16h)[j] = make_uint2(h0, h1);
        ((uint2*)g_Wk16l)[j] = make_uint2(l0, l1);
        return;
    }
    j -= NW4;
    if (j < NW4) {
        float4 v = ((const float4*)Wv)[j];
        ((uint2*)g_Wv16)[j] =
            make_uint2(pack_h2(v.x, v.y), pack_h2(v.z, v.w));
        return;
    }
    j -= NW4;
    if (j < NW4) {
        float4 v = ((const float4*)Wo)[j];
        uint32_t h0, l0, h1, l1;
        split2(v.x, v.y, h0, l0);
        split2(v.z, v.w, h1, l1);
        ((uint2*)g_Woh)[j] = make_uint2(h0, h1);
        ((uint2*)g_Wol)[j] = make_uint2(l0, l1);
    }
}

#define ROWB      80
#define TILE_A    (128 * ROWB)

// ===========================================================================
// fp16x2 GEMM: C = A[M,K] @ B[N,K]^T, A fp16 single, B fp16 hi/lo. 2 mma/frag.
// OMODE 2: fp16 single out. OMODE 3: fp16 hi/lo out.
// ===========================================================================
template<int OMODE>
__device__ __forceinline__
void gemm16_body(const __half* __restrict__ A,
                 const __half* __restrict__ Bh, const __half* __restrict__ Bl,
                 __half* __restrict__ Cf16, __half* __restrict__ Cf16l,
                 int M, int N, int K, int bm, int bn, uint32_t sbase)
{
    constexpr int BNR = 128;
    constexpr int TILE_BB = BNR * ROWB;
    constexpr int BUF_B = TILE_A + 2 * TILE_BB;      // 30720
    constexpr int AH = 0, BH = TILE_A, BL = TILE_A + TILE_BB;
    constexpr int NF = BNR / 16;

    const int tid  = threadIdx.x;
    const int lane = tid & 31;
    const int warp = tid >> 5;
    const int m0 = (warp >> 1) * 32;
    const int n0 = (warp & 1) * (BNR / 2);

    float acc[2][NF][4];
    #pragma unroll
    for (int mt = 0; mt < 2; mt++)
        #pragma unroll
        for (int nf = 0; nf < NF; nf++)
            #pragma unroll
            for (int e = 0; e < 4; e++) acc[mt][nf][e] = 0.0f;

    const int nchunk = K / 32;

    auto issue = [&](int c) {
        const uint32_t buf = sbase + (uint32_t)(c & 1) * BUF_B;
        const int kc = c * 32;
        #pragma unroll
        for (int j = 0; j < 6; j++) {                // 1536 chunks / 256
            const int idx = tid + j * 256;
            uint32_t dst;
            const __half* src;
            if (idx < 512) {
                const int row = idx >> 2, ch = idx & 3;
                dst = buf + AH + row * ROWB + ch * 16;
                src = &A[(size_t)(bm + row) * K + kc + ch * 8];
            } else if (idx < 1024) {
                const int r2 = idx - 512;
                const int row = r2 >> 2, ch = r2 & 3;
                dst = buf + BH + row * ROWB + ch * 16;
                src = &Bh[(size_t)(bn + row) * K + kc + ch * 8];
            } else {
                const int r2 = idx - 1024;
                const int row = r2 >> 2, ch = r2 & 3;
                dst = buf + BL + row * ROWB + ch * 16;
                src = &Bl[(size_t)(bn + row) * K + kc + ch * 8];
            }
            cp_async16(dst, src);
        }
        CP_COMMIT();
    };

    issue(0);

    const uint32_t lrow = (lane & 15);
    const uint32_t koff = (lane >> 4) * 16;

    for (int c = 0; c < nchunk; ++c) {
        CP_WAIT0();
        __syncthreads();
        if (c + 1 < nchunk) issue(c + 1);

        const uint32_t buf = sbase + (uint32_t)(c & 1) * BUF_B;
        #pragma unroll
        for (int ks = 0; ks < 2; ks++) {
            const uint32_t kb = ks * 32 + koff;
            uint32_t ah[2][4];
            #pragma unroll
            for (int mt = 0; mt < 2; mt++) {
                const uint32_t ro = (uint32_t)(m0 + mt * 16 + lrow) * ROWB + kb;
                ldsm_x4(ah[mt], buf + AH + ro);
            }
            uint32_t bh[NF / 2][4], bl[NF / 2][4];
            #pragma unroll
            for (int g = 0; g < NF / 2; g++) {
                const uint32_t ro = (uint32_t)(n0 + g * 16 + lrow) * ROWB + kb;
                ldsm_x4(bh[g], buf + BH + ro);
                ldsm_x4(bl[g], buf + BL + ro);
            }
            #pragma unroll
            for (int mt = 0; mt < 2; mt++) {
                #pragma unroll
                for (int g = 0; g < NF / 2; g++) {
                    mma_fp16(acc[mt][g * 2 + 0], ah[mt], bh[g][0], bh[g][2]);
                    mma_fp16(acc[mt][g * 2 + 0], ah[mt], bl[g][0], bl[g][2]);
                    mma_fp16(acc[mt][g * 2 + 1], ah[mt], bh[g][1], bh[g][3]);
                    mma_fp16(acc[mt][g * 2 + 1], ah[mt], bl[g][1], bl[g][3]);
                }
            }
        }
        __syncthreads();
    }

    #pragma unroll
    for (int mt = 0; mt < 2; mt++) {
        const int row = bm + m0 + mt * 16 + (lane >> 2);
        #pragma unroll
        for (int nf = 0; nf < NF; nf++) {
            const int col = bn + n0 + nf * 8 + (lane & 3) * 2;
            if (OMODE == 2) {
                *(uint32_t*)&Cf16[(size_t)row * N + col] =
                    pack_h2(acc[mt][nf][0], acc[mt][nf][1]);
                *(uint32_t*)&Cf16[(size_t)(row + 8) * N + col] =
                    pack_h2(acc[mt][nf][2], acc[mt][nf][3]);
            } else {
                uint32_t h0, l0, h1, l1;
                split2h(acc[mt][nf][0], acc[mt][nf][1], h0, l0);
                split2h(acc[mt][nf][2], acc[mt][nf][3], h1, l1);
                *(uint32_t*)&Cf16[(size_t)row * N + col]        = h0;
                *(uint32_t*)&Cf16l[(size_t)row * N + col]       = l0;
                *(uint32_t*)&Cf16[(size_t)(row + 8) * N + col]  = h1;
                *(uint32_t*)&Cf16l[(size_t)(row + 8) * N + col] = l1;
            }
        }
    }
}

#define GEMM16_SMEM (2 * (TILE_A + 2 * 128 * ROWB))  // 61440

__global__ __launch_bounds__(256, 2)
void gemm_qkv()
{
    extern __shared__ __align__(128) char dynsm[];
    const uint32_t sbase = smem_u32(dynsm);
    const int z = blockIdx.z;

    if (z == 0) {
        gemm16_body<2>(g_x16, g_Wq16h, g_Wq16l, g_Qt, nullptr,
                       S_LEN, DM, DM, blockIdx.x * 128, blockIdx.y * 128, sbase);
    } else if (z == 1) {
        gemm16_body<3>(g_x16, g_Wk16h, g_Wk16l, g_K16h, g_K16l,
                       S_LEN, DM, DM, blockIdx.x * 128, blockIdx.y * 128, sbase);
    } else {
        // V^T = Wv @ x^T : A = Wv (fp16 single), B = x (fp16 hi/lo)
        gemm16_body<2>(g_Wv16, g_x16h, g_x16l, g_Vt, nullptr,
                       DM, S_LEN, DM, blockIdx.y * 128, blockIdx.x * 128, sbase);
    }
}

// ===========================================================================
// bf16x3 out-projection (unchanged): out = ctx @ Wo^T, 128x96 tiles.
// ===========================================================================
__global__ __launch_bounds__(256, 2)
void gemm_out(float* __restrict__ out)
{
    extern __shared__ __align__(128) char dynsm[];
    const uint32_t sbase = smem_u32(dynsm);
    constexpr int BNR = 96;
    constexpr int TILE_BB = BNR * ROWB;
    constexpr int BUF_B = 2 * TILE_A + 2 * TILE_BB;
    constexpr int AHI = 0, ALO = TILE_A, BHI = 2 * TILE_A, BLO = 2 * TILE_A + TILE_BB;
    constexpr int NF = BNR / 16;
    constexpr int NCP = (1024 + BNR * 8) / 256;   // 7

    const int tid  = threadIdx.x;
    const int lane = tid & 31;
    const int warp = tid >> 5;
    const int m0 = (warp >> 1) * 32;
    const int n0 = (warp & 1) * (BNR / 2);
    const int bm = blockIdx.x * 128;
    const int bn = blockIdx.y * BNR;
    const int N = DM, K = DM;

    float acc[2][NF][4];
    #pragma unroll
    for (int mt = 0; mt < 2; mt++)
        #pragma unroll
        for (int nf = 0; nf < NF; nf++)
            #pragma unroll
            for (int e = 0; e < 4; e++) acc[mt][nf][e] = 0.0f;

    const int nchunk = K / 32;

    auto issue = [&](int c) {
        const uint32_t buf = sbase + (uint32_t)(c & 1) * BUF_B;
        const int kc = c * 32;
        #pragma unroll
        for (int j = 0; j < NCP; j++) {
            const int idx = tid + j * 256;
            uint32_t dst;
            const __nv_bfloat16* src;
            if (idx < 512) {
                const int row = idx >> 2, ch = idx & 3;
                dst = buf + AHI + row * ROWB + ch * 16;
                src = &g_ctxh[(size_t)(bm + row) * K + kc + ch * 8];
            } else if (idx < 1024) {
                const int r2 = idx - 512;
                const int row = r2 >> 2, ch = r2 & 3;
                dst = buf + ALO + row * ROWB + ch * 16;
                src = &g_ctxl[(size_t)(bm + row) * K + kc + ch * 8];
            } else if (idx < 1024 + BNR * 4) {
                const int r2 = idx - 1024;
                const int row = r2 >> 2, ch = r2 & 3;
                dst = buf + BHI + row * ROWB + ch * 16;
                src = &g_Woh[(size_t)(bn + row) * K + kc + ch * 8];
            } else {
                const int r2 = idx - (1024 + BNR * 4);
                const int row = r2 >> 2, ch = r2 & 3;
                dst = buf + BLO + row * ROWB + ch * 16;
                src = &g_Wol[(size_t)(bn + row) * K + kc + ch * 8];
            }
            cp_async16(dst, src);
        }
        CP_COMMIT();
    };

    issue(0);

    const uint32_t lrow = (lane & 15);
    const uint32_t koff = (lane >> 4) * 16;

    for (int c = 0; c < nchunk; ++c) {
        CP_WAIT0();
        __syncthreads();
        if (c + 1 < nchunk) issue(c + 1);

        const uint32_t buf = sbase + (uint32_t)(c & 1) * BUF_B;
        #pragma unroll
        for (int ks = 0; ks < 2; ks++) {
            const uint32_t kb = ks * 32 + koff;
            uint32_t ah[2][4], al[2][4];
            #pragma unroll
            for (int mt = 0; mt < 2; mt++) {
                const uint32_t ro = (uint32_t)(m0 + mt * 16 + lrow) * ROWB + kb;
                ldsm_x4(ah[mt], buf + AHI + ro);
                ldsm_x4(al[mt], buf + ALO + ro);
            }
            uint32_t bh[NF / 2][4], bl[NF / 2][4];
            #pragma unroll
            for (int g = 0; g < NF / 2; g++) {
                const uint32_t ro = (uint32_t)(n0 + g * 16 + lrow) * ROWB + kb;
                ldsm_x4(bh[g], buf + BHI + ro);
                ldsm_x4(bl[g], buf + BLO + ro);
            }
            #pragma unroll
            for (int mt = 0; mt < 2; mt++) {
                #pragma unroll
                for (int g = 0; g < NF / 2; g++) {
                    mma_bf16(acc[mt][g * 2 + 0], ah[mt], bh[g][0], bh[g][2]);
                    mma_bf16(acc[mt][g * 2 + 0], ah[mt], bl[g][0], bl[g][2]);
                    mma_bf16(acc[mt][g * 2 + 0], al[mt], bh[g][0], bh[g][2]);
                    mma_bf16(acc[mt][g * 2 + 1], ah[mt], bh[g][1], bh[g][3]);
                    mma_bf16(acc[mt][g * 2 + 1], ah[mt], bl[g][1], bl[g][3]);
                    mma_bf16(acc[mt][g * 2 + 1], al[mt], bh[g][1], bh[g][3]);
                }
            }
        }
        __syncthreads();
    }

    #pragma unroll
    for (int mt = 0; mt < 2; mt++) {
        const int row = bm + m0 + mt * 16 + (lane >> 2);
        #pragma unroll
        for (int nf = 0; nf < NF; nf++) {
            const int col = bn + n0 + nf * 8 + (lane & 3) * 2;
            *(float2*)&out[(size_t)row * N + col] =
                make_float2(acc[mt][nf][0], acc[mt][nf][1]);
            *(float2*)&out[(size_t)(row + 8) * N + col] =
                make_float2(acc[mt][nf][2], acc[mt][nf][3]);
        }
    }
}

#define GEMM_SMEM_96 (2 * (2 * TILE_A + 2 * 96 * ROWB))    // 71680

// ===========================================================================
// Attention (unchanged from R16): QK fp16x2, PV fp16, split-K + LPT.
// ===========================================================================
#define AROWB 144
#define AQ    0
#define AKV   (128 * AROWB)              // 18432
#define KVSTG 24576
#define KH_O  0
#define KL_O  8192
#define V_O   16384
#define ATTN_SMEM (AKV + 2 * KVSTG)      // 67584

__global__ __launch_bounds__(256, 2)
void attn_tc()
{
    extern __shared__ __align__(128) char dynbuf[];
    const uint32_t sb = smem_u32(dynbuf);

    const int tid  = threadIdx.x;
    const int lane = tid & 31;
    const int warp = tid >> 5;
    const int wr   = warp * 16;

    const int type = blockIdx.x / NH;
    const int h    = blockIdx.x % NH;
    const int qb   = c_qb[type];
    const int t0   = c_t0[type];
    const int t1   = c_t1[type];
    const int part = c_pt[type];
    const int q0   = qb * 128;

    // ---- load Q tile (fp16 single) ----
    #pragma unroll
    for (int i = 0; i < 4; i++) {
        const int idx = tid + i * 256;
        const int row = idx >> 3;
        const int ch  = idx & 7;
        const uint32_t soff = (uint32_t)row * AROWB + ch * 16;
        uint4 v = *(const uint4*)&g_Qt[(size_t)(q0 + row) * DM + h * 64 + ch * 8];
        sts_v4(sb + AQ + soff, v);
    }

    auto issue_kv = [&](int t) {
        const uint32_t kvb = sb + AKV + (uint32_t)(t & 1) * KVSTG;
        const int k0 = t * 64;
        #pragma unroll
        for (int j = 0; j < 6; j++) {
            const int idx = tid + j * 256;
            const int arr = idx >> 9;
            const int rem2 = idx & 511;
            const int row = rem2 >> 3;
            const int c   = rem2 & 7;
            const uint32_t dst = kvb + (uint32_t)arr * 8192 + row * 128 +
                                 ((uint32_t)(c ^ (row & 7)) << 4);
            const void* src;
            if (arr == 0)      src = &g_K16h[(size_t)(k0 + row) * DM + h * 64 + c * 8];
            else if (arr == 1) src = &g_K16l[(size_t)(k0 + row) * DM + h * 64 + c * 8];
            else               src = &g_Vt[(size_t)(h * 64 + row) * S_LEN + k0 + c * 8];
            cp_async16(dst, src);
        }
        CP_COMMIT();
    };

    issue_kv(t0);

    float o[8][4];
    #pragma unroll
    for (int f = 0; f < 8; f++)
        #pragma unroll
        for (int e = 0; e < 4; e++) o[f][e] = 0.0f;
    float m_s[2] = {-1e30f, -1e30f};
    float l_s[2] = {0.0f, 0.0f};

    const int row0 = q0 + wr + (lane >> 2);
    const int row1 = row0 + 8;
    const uint32_t lrow = (lane & 15);
    const uint32_t koff = (lane >> 4) * 16;

    for (int t = t0; t < t1; ++t) {
        const int k0 = t * 64;
        CP_WAIT0();
        __syncthreads();
        if (t + 1 < t1) issue_kv(t + 1);

        const uint32_t kvb = sb + AKV + (uint32_t)(t & 1) * KVSTG;

        float sacc[8][4];
        #pragma unroll
        for (int f = 0; f < 8; f++)
            #pragma unroll
            for (int e = 0; e < 4; e++) sacc[f][e] = 0.0f;

        #pragma unroll
        for (int ks = 0; ks < 4; ks++) {
            uint32_t qh[4];
            const uint32_t qoff = (uint32_t)(wr + lrow) * AROWB + ks * 32 + koff;
            ldsm_x4(qh, sb + AQ + qoff);
            const uint32_t cidx = ks * 2 + (lane >> 4);
            #pragma unroll
            for (int g = 0; g < 4; g++) {
                const uint32_t row = g * 16 + lrow;
                const uint32_t ro = row * 128 + ((cidx ^ (row & 7)) << 4);
                uint32_t kh[4], kl[4];
                ldsm_x4(kh, kvb + KH_O + ro);
                ldsm_x4(kl, kvb + KL_O + ro);
                mma_fp16(sacc[g * 2 + 0], qh, kh[0], kh[2]);
                mma_fp16(sacc[g * 2 + 0], qh, kl[0], kl[2]);
                mma_fp16(sacc[g * 2 + 1], qh, kh[1], kh[3]);
                mma_fp16(sacc[g * 2 + 1], qh, kl[1], kl[3]);
            }
        }

        const float scale = 0.125f;
        if (t >= 2 * qb) {
            #pragma unroll
            for (int f = 0; f < 8; f++) {
                const int cb = k0 + f * 8 + (lane & 3) * 2;
                sacc[f][0] = (cb     > row0) ? -1e30f : sacc[f][0] * scale;
                sacc[f][1] = (cb + 1 > row0) ? -1e30f : sacc[f][1] * scale;
                sacc[f][2] = (cb     > row1) ? -1e30f : sacc[f][2] * scale;
                sacc[f][3] = (cb + 1 > row1) ? -1e30f : sacc[f][3] * scale;
            }
        } else {
            #pragma unroll
            for (int f = 0; f < 8; f++)
                #pragma unroll
                for (int e = 0; e < 4; e++) sacc[f][e] *= scale;
        }

        float rm0 = -1e30f, rm1 = -1e30f;
        #pragma unroll
        for (int f = 0; f < 8; f++) {
            rm0 = fmaxf(rm0, fmaxf(sacc[f][0], sacc[f][1]));
            rm1 = fmaxf(rm1, fmaxf(sacc[f][2], sacc[f][3]));
        }
        #pragma unroll
        for (int off = 1; off < 4; off <<= 1) {
            rm0 = fmaxf(rm0, __shfl_xor_sync(0xffffffffu, rm0, off));
            rm1 = fmaxf(rm1, __shfl_xor_sync(0xffffffffu, rm1, off));
        }
        const float mn0 = fmaxf(m_s[0], rm0);
        const float mn1 = fmaxf(m_s[1], rm1);
        const float al0 = __expf(m_s[0] - mn0);
        const float al1 = __expf(m_s[1] - mn1);
        float rs0 = 0.0f, rs1 = 0.0f;
        #pragma unroll
        for (int f = 0; f < 8; f++) {
            sacc[f][0] = round_h(__expf(sacc[f][0] - mn0));
            sacc[f][1] = round_h(__expf(sacc[f][1] - mn0));
            sacc[f][2] = round_h(__expf(sacc[f][2] - mn1));
            sacc[f][3] = round_h(__expf(sacc[f][3] - mn1));
            rs0 += sacc[f][0] + sacc[f][1];
            rs1 += sacc[f][2] + sacc[f][3];
        }
        #pragma unroll
        for (int off = 1; off < 4; off <<= 1) {
            rs0 += __shfl_xor_sync(0xffffffffu, rs0, off);
            rs1 += __shfl_xor_sync(0xffffffffu, rs1, off);
        }
        l_s[0] = l_s[0] * al0 + rs0;
        l_s[1] = l_s[1] * al1 + rs1;
        m_s[0] = mn0;
        m_s[1] = mn1;
        #pragma unroll
        for (int f = 0; f < 8; f++) {
            o[f][0] *= al0; o[f][1] *= al0;
            o[f][2] *= al1; o[f][3] *= al1;
        }

        #pragma unroll
        for (int ks = 0; ks < 4; ks++) {
            const float* s0 = sacc[2 * ks];
            const float* s1 = sacc[2 * ks + 1];
            uint32_t ph[4];
            ph[0] = pack_h2(s0[0], s0[1]);
            ph[1] = pack_h2(s0[2], s0[3]);
            ph[2] = pack_h2(s1[0], s1[1]);
            ph[3] = pack_h2(s1[2], s1[3]);
            const uint32_t cidx = ks * 2 + (lane >> 4);
            #pragma unroll
            for (int g = 0; g < 4; g++) {
                const uint32_t row = g * 16 + lrow;
                const uint32_t ro = row * 128 + ((cidx ^ (row & 7)) << 4);
                uint32_t vv[4];
                ldsm_x4(vv, kvb + V_O + ro);
                mma_fp16(o[g * 2 + 0], ph, vv[0], vv[2]);
                mma_fp16(o[g * 2 + 1], ph, vv[1], vv[3]);
            }
        }
    }

    if (part == 255) {
        const float inv0 = 1.0f / l_s[0];
        const float inv1 = 1.0f / l_s[1];
        #pragma unroll
        for (int f = 0; f < 8; f++) {
            const int col = h * 64 + f * 8 + (lane & 3) * 2;
            uint32_t h0, l0, h1, l1;
            split2(o[f][0] * inv0, o[f][1] * inv0, h0, l0);
            split2(o[f][2] * inv1, o[f][3] * inv1, h1, l1);
            *(uint32_t*)&g_ctxh[(size_t)row0 * DM + col] = h0;
            *(uint32_t*)&g_ctxl[(size_t)row0 * DM + col] = l0;
            *(uint32_t*)&g_ctxh[(size_t)row1 * DM + col] = h1;
            *(uint32_t*)&g_ctxl[(size_t)row1 * DM + col] = l1;
        }
    } else {
        const int base = (h * 20 + (qb - 12)) * 128;
        const int r0 = base + (row0 - q0);
        const int r1 = base + (row1 - q0);
        g_pm[part][r0] = m_s[0];
        g_pl[part][r0] = l_s[0];
        g_pm[part][r1] = m_s[1];
        g_pl[part][r1] = l_s[1];
        #pragma unroll
        for (int f = 0; f < 8; f++) {
            const int d = f * 8 + (lane & 3) * 2;
            *(float2*)&g_pO[part][(size_t)r0 * DK + d] = make_float2(o[f][0], o[f][1]);
            *(float2*)&g_pO[part][(size_t)r1 * DK + d] = make_float2(o[f][2], o[f][3]);
        }
    }
}

// ---- merge split-K partials (unchanged) ----
__global__ __launch_bounds__(256)
void attn_merge()
{
    const int tid = blockIdx.x * 256 + threadIdx.x;
    if (tid >= NSPLIT_ROWS * 32) return;
    const int rid = tid >> 5;
    const int d   = (tid & 31) * 2;

    const int h    = rid / (20 * 128);
    const int qbo  = (rid >> 7) % 20;
    const int qb   = 12 + qbo;
    const int nparts = (qb >= 24) ? 3 : 2;

    float M = fmaxf(g_pm[0][rid], g_pm[1][rid]);
    if (nparts == 3) M = fmaxf(M, g_pm[2][rid]);

    float lsum = 0.0f, va = 0.0f, vb = 0.0f;
    #pragma unroll
    for (int p = 0; p < 3; p++) {
        if (p >= nparts) break;
        const float w = __expf(g_pm[p][rid] - M);
        lsum += w * g_pl[p][rid];
        const float2 a = *(const float2*)&g_pO[p][(size_t)rid * DK + d];
        va += w * a.x;
        vb += w * a.y;
    }
    const float inv = 1.0f / lsum;
    va *= inv; vb *= inv;

    const int r    = rid & 127;
    const int grow = qb * 128 + r;
    const int col  = h * 64 + d;

    uint32_t hi, lo;
    split2(va, vb, hi, lo);
    *(uint32_t*)&g_ctxh[(size_t)grow * DM + col] = hi;
    *(uint32_t*)&g_ctxl[(size_t)grow * DM + col] = lo;
}

// ---------------------------------------------------------------------------
extern "C" void kernel_launch(void* const* d_in, const int* in_sizes, int n_in,
                              void* d_out, int out_size)
{
    const float* x  = (const float*)d_in[0];
    const float* Wq = (const float*)d_in[1];
    const float* Wk = (const float*)d_in[2];
    const float* Wv = (const float*)d_in[3];
    const float* Wo = (const float*)d_in[4];
    float* out = (float*)d_out;

    cudaFuncSetAttribute(gemm_qkv,
                         cudaFuncAttributeMaxDynamicSharedMemorySize, GEMM16_SMEM);
    cudaFuncSetAttribute(gemm_out,
                         cudaFuncAttributeMaxDynamicSharedMemorySize, GEMM_SMEM_96);
    cudaFuncSetAttribute(attn_tc,
                         cudaFuncAttributeMaxDynamicSharedMemorySize, ATTN_SMEM);

    const int ntot4 = NX4 + 4 * NW4;
    split_all<<<(ntot4 + 255) / 256, 256>>>(x, Wq, Wk, Wv, Wo);

    gemm_qkv<<<dim3(S_LEN / 128, DM / 128, 3), 256, GEMM16_SMEM>>>();

    attn_tc<<<dim3(ATTN_JOBS), 256, ATTN_SMEM>>>();
    attn_merge<<<(NSPLIT_ROWS * 32 + 255) / 256, 256>>>();

    gemm_out<<<dim3(S_LEN / 128, DM / 96), 256, GEMM_SMEM_96>>>(out);
}